// round 2
// baseline (speedup 1.0000x reference)
#include <cuda_runtime.h>

#define PLEN 2048
#define BATCH 2
#define NH 8
#define DH 64
#define DM 512

// Scratch (allocation-free: __device__ globals)
__device__ float g_q[BATCH * PLEN * DM];
__device__ float g_k[BATCH * PLEN * DM];
__device__ float g_v[BATCH * PLEN * DM];
__device__ float g_oh[BATCH * PLEN * DM];
__device__ float g_S[(size_t)BATCH * NH * PLEN * PLEN];  // 268 MB: scores, then post-mix attn (in place)

// ---------------------------------------------------------------------------
// Generic 64x64 tile GEMM (fp32, 256 threads, 4x4 per thread, BK=16)
// TB=false: C = A[MxK] * B[KxN]   (both row-major)
// TB=true : C = A[MxK] * B[NxK]^T (both row-major, K contiguous)
// ---------------------------------------------------------------------------
template <bool TB>
__device__ __forceinline__ void gemm64_tile(
    const float* __restrict__ A, int lda,
    const float* __restrict__ B, int ldb,
    float* __restrict__ C, int ldc,
    int K, float alpha, int m0, int n0)
{
    __shared__ float As[16][68];
    __shared__ float Bs[16][68];

    const int tid = threadIdx.x;       // 0..255
    const int tx = tid & 15;           // n micro-tile
    const int ty = tid >> 4;           // m micro-tile
    const int lr = tid >> 2;           // 0..63  (row for transposed loads)
    const int lc = (tid & 3) << 2;     // 0,4,8,12 (k offset for transposed loads)

    float acc[4][4];
#pragma unroll
    for (int i = 0; i < 4; i++)
#pragma unroll
        for (int j = 0; j < 4; j++) acc[i][j] = 0.f;

    for (int k0 = 0; k0 < K; k0 += 16) {
        // global loads for this chunk
        float4 av = *(const float4*)(A + (size_t)(m0 + lr) * lda + k0 + lc);
        float4 bv;
        if (TB) {
            bv = *(const float4*)(B + (size_t)(n0 + lr) * ldb + k0 + lc);
        } else {
            bv = *(const float4*)(B + (size_t)(k0 + ty) * ldb + n0 + (tx << 2));
        }
        __syncthreads();  // previous compute done before overwriting smem
        As[lc + 0][lr] = av.x;
        As[lc + 1][lr] = av.y;
        As[lc + 2][lr] = av.z;
        As[lc + 3][lr] = av.w;
        if (TB) {
            Bs[lc + 0][lr] = bv.x;
            Bs[lc + 1][lr] = bv.y;
            Bs[lc + 2][lr] = bv.z;
            Bs[lc + 3][lr] = bv.w;
        } else {
            *(float4*)&Bs[ty][tx << 2] = bv;
        }
        __syncthreads();
#pragma unroll
        for (int kk = 0; kk < 16; kk++) {
            float4 a4 = *(const float4*)&As[kk][ty << 2];
            float4 b4 = *(const float4*)&Bs[kk][tx << 2];
            float a_[4] = {a4.x, a4.y, a4.z, a4.w};
            float b_[4] = {b4.x, b4.y, b4.z, b4.w};
#pragma unroll
            for (int i = 0; i < 4; i++)
#pragma unroll
                for (int j = 0; j < 4; j++) acc[i][j] += a_[i] * b_[j];
        }
    }

#pragma unroll
    for (int i = 0; i < 4; i++) {
        float* Crow = C + (size_t)(m0 + (ty << 2) + i) * ldc + n0 + (tx << 2);
#pragma unroll
        for (int j = 0; j < 4; j++) Crow[j] = acc[i][j] * alpha;
    }
}

// ---------------------------------------------------------------------------
// Stage 1: Q/K/V projections.  grid (8, 64, 3), 256 thr
// ---------------------------------------------------------------------------
__global__ __launch_bounds__(256) void k_qkv(
    const float* __restrict__ x,
    const float* __restrict__ Wq,
    const float* __restrict__ Wk,
    const float* __restrict__ Wv)
{
    int nt = blockIdx.x, mt = blockIdx.y, which = blockIdx.z;
    const float* W = (which == 0) ? Wq : (which == 1) ? Wk : Wv;
    float* O = (which == 0) ? g_q : (which == 1) ? g_k : g_v;
    float alpha = (which == 0) ? 0.125f : 1.0f;  // q /= sqrt(64)
    gemm64_tile<false>(x, DM, W, DM, O, DM, DM, alpha, mt * 64, nt * 64);
}

// ---------------------------------------------------------------------------
// Stage 2: raw scores S[b,h] = q_h @ k_h^T.  grid (32, 32, 16), 256 thr
// ---------------------------------------------------------------------------
__global__ __launch_bounds__(256) void k_scores()
{
    int jt = blockIdx.x, it = blockIdx.y, z = blockIdx.z;
    int b = z >> 3, h = z & 7;
    const float* A = g_q + (size_t)b * PLEN * DM + h * DH;
    const float* B = g_k + (size_t)b * PLEN * DM + h * DH;
    float* C = g_S + (size_t)z * PLEN * PLEN;
    gemm64_tile<true>(A, DM, B, DM, C, PLEN, DH, 1.0f, it * 64, jt * 64);
}

// ---------------------------------------------------------------------------
// Stage 3: head-mix (W1) -> softmax -> head-mix (W2, /l folded), in place.
// One CTA per (b, i): reads S[b,:,i,:], writes A3[b,:,i,:].
// grid (2048, 2), 512 thr, 64 KB dynamic smem
// ---------------------------------------------------------------------------
__device__ __forceinline__ float block_reduce_max(float v, float* red)
{
#pragma unroll
    for (int o = 16; o; o >>= 1) v = fmaxf(v, __shfl_xor_sync(0xffffffffu, v, o));
    int w = threadIdx.x >> 5;
    if ((threadIdx.x & 31) == 0) red[w] = v;
    __syncthreads();
    if (threadIdx.x < 16) {
        v = red[threadIdx.x];
#pragma unroll
        for (int o = 8; o; o >>= 1) v = fmaxf(v, __shfl_xor_sync(0xffffu, v, o));
        if (threadIdx.x == 0) red[0] = v;
    }
    __syncthreads();
    v = red[0];
    __syncthreads();
    return v;
}

__device__ __forceinline__ float block_reduce_sum(float v, float* red)
{
#pragma unroll
    for (int o = 16; o; o >>= 1) v += __shfl_xor_sync(0xffffffffu, v, o);
    int w = threadIdx.x >> 5;
    if ((threadIdx.x & 31) == 0) red[w] = v;
    __syncthreads();
    if (threadIdx.x < 16) {
        v = red[threadIdx.x];
#pragma unroll
        for (int o = 8; o; o >>= 1) v += __shfl_xor_sync(0xffffu, v, o);
        if (threadIdx.x == 0) red[0] = v;
    }
    __syncthreads();
    v = red[0];
    __syncthreads();
    return v;
}

__global__ __launch_bounds__(512) void k_mix_softmax(
    const float* __restrict__ W1, const float* __restrict__ W2)
{
    extern __shared__ float smix[];  // [8][2048]
    __shared__ float red[16];
    __shared__ float w1s[64];
    __shared__ float lstat[8];
    __shared__ float w2l[64];

    const int tid = threadIdx.x;  // 512
    const int i = blockIdx.x;
    const int b = blockIdx.y;

    if (tid < 64) w1s[tid] = W1[tid];
    __syncthreads();

    float* Srow = g_S + (size_t)b * NH * PLEN * PLEN + (size_t)i * PLEN;  // + h*P*P

    // mix1: smix[g][j] = sum_h W1[h,g] * S[b,h,i,j]
#pragma unroll
    for (int j0 = 0; j0 < PLEN; j0 += 512) {
        int j = j0 + tid;
        float r[8];
#pragma unroll
        for (int h = 0; h < 8; h++) r[h] = Srow[(size_t)h * PLEN * PLEN + j];
#pragma unroll
        for (int g = 0; g < 8; g++) {
            float a = 0.f;
#pragma unroll
            for (int h = 0; h < 8; h++) a += w1s[h * 8 + g] * r[h];
            smix[g * PLEN + j] = a;
        }
    }
    __syncthreads();

    // softmax per g (exp in place; keep l)
    for (int g = 0; g < 8; g++) {
        float m = -1e30f;
        for (int j = tid; j < PLEN; j += 512) m = fmaxf(m, smix[g * PLEN + j]);
        m = block_reduce_max(m, red);
        float l = 0.f;
        for (int j = tid; j < PLEN; j += 512) {
            float e = __expf(smix[g * PLEN + j] - m);
            smix[g * PLEN + j] = e;
            l += e;
        }
        l = block_reduce_sum(l, red);
        if (tid == 0) lstat[g] = l;
        __syncthreads();
    }

    // w2l[g][g'] = W2[g,g'] / l_g
    if (tid < 64) w2l[tid] = W2[tid] / lstat[tid >> 3];
    __syncthreads();

    // mix2 + writeback (in place over the same rows)
#pragma unroll
    for (int j0 = 0; j0 < PLEN; j0 += 512) {
        int j = j0 + tid;
        float e[8];
#pragma unroll
        for (int g = 0; g < 8; g++) e[g] = smix[g * PLEN + j];
#pragma unroll
        for (int gp = 0; gp < 8; gp++) {
            float a = 0.f;
#pragma unroll
            for (int g = 0; g < 8; g++) a += w2l[g * 8 + gp] * e[g];
            Srow[(size_t)gp * PLEN * PLEN + j] = a;
        }
    }
}

// ---------------------------------------------------------------------------
// Stage 4: out_heads[b,g] = A3[b,g] @ v[b,:,g*64:...]. grid (32, 1, 16), 256 thr
// ---------------------------------------------------------------------------
__global__ __launch_bounds__(256) void k_pv()
{
    int it = blockIdx.x, z = blockIdx.z;
    int b = z >> 3, g = z & 7;
    const float* A = g_S + (size_t)z * PLEN * PLEN;
    const float* B = g_v + (size_t)b * PLEN * DM + g * DH;
    float* C = g_oh + (size_t)b * PLEN * DM + g * DH;
    gemm64_tile<false>(A, PLEN, B, DM, C, DM, PLEN, 1.0f, it * 64, 0);
}

// ---------------------------------------------------------------------------
// Stage 5: out = out_heads @ Wproj. grid (8, 64), 256 thr
// ---------------------------------------------------------------------------
__global__ __launch_bounds__(256) void k_proj(const float* __restrict__ Wp,
                                              float* __restrict__ out)
{
    gemm64_tile<false>(g_oh, DM, Wp, DM, out, DM, DM, 1.0f,
                       blockIdx.y * 64, blockIdx.x * 64);
}

// ---------------------------------------------------------------------------
extern "C" void kernel_launch(void* const* d_in, const int* in_sizes, int n_in,
                              void* d_out, int out_size)
{
    const float* x     = (const float*)d_in[0];
    const float* Wq    = (const float*)d_in[1];
    const float* Wk    = (const float*)d_in[2];
    const float* Wv    = (const float*)d_in[3];
    const float* W1    = (const float*)d_in[4];
    const float* W2    = (const float*)d_in[5];
    const float* Wproj = (const float*)d_in[6];
    float* out = (float*)d_out;

    cudaFuncSetAttribute(k_mix_softmax,
                         cudaFuncAttributeMaxDynamicSharedMemorySize, 65536);

    k_qkv<<<dim3(8, 64, 3), 256>>>(x, Wq, Wk, Wv);
    k_scores<<<dim3(32, 32, 16), 256>>>();
    k_mix_softmax<<<dim3(2048, 2, 1), 512, 65536>>>(W1, W2);
    k_pv<<<dim3(32, 1, 16), 256>>>();
    k_proj<<<dim3(8, 64), 256>>>(Wproj, out);
}

// round 4
// speedup vs baseline: 1.1553x; 1.1553x over previous
#include <cuda_runtime.h>
#include <cuda_bf16.h>
#include <cstdint>

#define PLEN 2048
#define BATCH 2
#define NH 8
#define DH 64
#define DM 512

// ---------------------------------------------------------------------------
// Scratch (allocation-free: __device__ globals)
// ---------------------------------------------------------------------------
__device__ float g_q[BATCH * PLEN * DM];
__device__ float g_k[BATCH * PLEN * DM];
__device__ float g_v[BATCH * PLEN * DM];
__device__ float g_oh[BATCH * PLEN * DM];
__device__ float g_vt[BATCH * DM * PLEN];          // V transposed: [b, d(512), j(2048)]
__device__ float g_wqt[DM * DM];
__device__ float g_wkt[DM * DM];
__device__ float g_wvt[DM * DM];
__device__ float g_wpt[DM * DM];
__device__ float g_S[(size_t)BATCH * NH * PLEN * PLEN];  // 268 MB scores / post-mix attn

// ---------------------------------------------------------------------------
// Warp MMA helpers (plain sm_80+ PTX: assembles for compute_103 non-'a')
// ---------------------------------------------------------------------------
__device__ __forceinline__ uint32_t smem_u32(const void* p) {
    uint32_t a;
    asm("{ .reg .u64 t; cvta.to.shared.u64 t, %1; cvt.u32.u64 %0, t; }" : "=r"(a) : "l"(p));
    return a;
}

#define LDSM4(r, addr)                                                         \
    asm volatile("ldmatrix.sync.aligned.m8n8.x4.shared.b16 {%0,%1,%2,%3}, [%4];" \
                 : "=r"((r)[0]), "=r"((r)[1]), "=r"((r)[2]), "=r"((r)[3])      \
                 : "r"(addr))

#define MMA16816(d, a, b)                                                      \
    asm volatile("mma.sync.aligned.m16n8k16.row.col.f32.bf16.bf16.f32 "        \
                 "{%0,%1,%2,%3}, {%4,%5,%6,%7}, {%8,%9}, {%0,%1,%2,%3};"       \
                 : "+f"((d)[0]), "+f"((d)[1]), "+f"((d)[2]), "+f"((d)[3])      \
                 : "r"((a)[0]), "r"((a)[1]), "r"((a)[2]), "r"((a)[3]),         \
                   "r"((b)[0]), "r"((b)[1]))

// Split one float4 into bf16 hi / lo pairs and store at element offset `off`
// (row-padded smem, 4 consecutive elements).
__device__ __forceinline__ void split_store(float4 v, __nv_bfloat16* hi,
                                            __nv_bfloat16* lo, int off)
{
    __nv_bfloat16 hx = __float2bfloat16_rn(v.x), hy = __float2bfloat16_rn(v.y);
    __nv_bfloat16 hz = __float2bfloat16_rn(v.z), hw = __float2bfloat16_rn(v.w);
    __nv_bfloat162 h01; h01.x = hx; h01.y = hy;
    __nv_bfloat162 h23; h23.x = hz; h23.y = hw;
    __nv_bfloat162 l01, l23;
    l01.x = __float2bfloat16_rn(v.x - __bfloat162float(hx));
    l01.y = __float2bfloat16_rn(v.y - __bfloat162float(hy));
    l23.x = __float2bfloat16_rn(v.z - __bfloat162float(hz));
    l23.y = __float2bfloat16_rn(v.w - __bfloat162float(hw));
    *(__nv_bfloat162*)(hi + off)     = h01;
    *(__nv_bfloat162*)(hi + off + 2) = h23;
    *(__nv_bfloat162*)(lo + off)     = l01;
    *(__nv_bfloat162*)(lo + off + 2) = l23;
}

// ---------------------------------------------------------------------------
// HMMA bf16-split NT GEMM:  C[M,N] = alpha * A[M,K] * B[N,K]^T   (fp32 I/O)
// CTA tile 128 x NT, K-chunk 32, 256 threads (8 warps).
// NT=128: warps 2x4 (warp tile 64x32). NT=64: warps 4x2 (warp tile 32x32).
// ---------------------------------------------------------------------------
#define KC 32
#define SRS 40  // smem row stride in bf16 elements (80 bytes, conflict-free ldmatrix)

template <int NT>
__device__ void hmma_gemm(const float* __restrict__ A, int lda,
                          const float* __restrict__ B, int ldb,
                          float* __restrict__ C, int ldc,
                          int K, float alpha, int m0, int n0)
{
    constexpr int WN = (NT == 128) ? 4 : 2;     // warps along n
    constexpr int WM = 8 / WN;                  // warps along m
    constexpr int MT = 128 / WM;                // warp m tile (64 or 32)
    constexpr int MF = MT / 16;                 // m frags (4 or 2)

    __shared__ __align__(16) __nv_bfloat16 sAh[128 * SRS];
    __shared__ __align__(16) __nv_bfloat16 sAl[128 * SRS];
    __shared__ __align__(16) __nv_bfloat16 sBh[NT * SRS];
    __shared__ __align__(16) __nv_bfloat16 sBl[NT * SRS];

    const int tid = threadIdx.x;
    const int wid = tid >> 5, lane = tid & 31;
    const int wm = wid / WN, wn = wid % WN;

    const uint32_t uAh = smem_u32(sAh), uAl = smem_u32(sAl);
    const uint32_t uBh = smem_u32(sBh), uBl = smem_u32(sBl);

    // ldmatrix lane address components (bytes)
    const uint32_t aRow = (uint32_t)(wm * MT + (lane & 15)) * (SRS * 2);
    const uint32_t aCol = (uint32_t)(lane >> 4) * 16;                 // k-half select
    const uint32_t bRow = (uint32_t)(wn * 32 + ((lane >> 4) << 3) + (lane & 7)) * (SRS * 2);
    const uint32_t bCol = (uint32_t)((lane >> 3) & 1) * 16;           // k-half select

    float acc[MF][4][4];
#pragma unroll
    for (int i = 0; i < MF; i++)
#pragma unroll
        for (int j = 0; j < 4; j++)
#pragma unroll
            for (int t = 0; t < 4; t++) acc[i][j][t] = 0.f;

    const int nch = K / KC;
    for (int ch = 0; ch < nch; ch++) {
        const int k0 = ch * KC;
        // ---- load + split A: 128 x 32 ----
#pragma unroll
        for (int i = tid; i < 128 * 8; i += 256) {
            int r = i >> 3, c4 = (i & 7) << 2;
            float4 v = *(const float4*)(A + (size_t)(m0 + r) * lda + k0 + c4);
            split_store(v, sAh, sAl, r * SRS + c4);
        }
        // ---- load + split B: NT x 32 ----
#pragma unroll
        for (int i = tid; i < NT * 8; i += 256) {
            int r = i >> 3, c4 = (i & 7) << 2;
            float4 v = *(const float4*)(B + (size_t)(n0 + r) * ldb + k0 + c4);
            split_store(v, sBh, sBl, r * SRS + c4);
        }
        __syncthreads();

#pragma unroll
        for (int ks = 0; ks < 2; ks++) {
            const uint32_t kb = (uint32_t)(ks * 16 * 2);  // 16 bf16 = 32 bytes
            uint32_t ah[MF][4], al[MF][4], bh[4][2], bl[4][2];
#pragma unroll
            for (int mf = 0; mf < MF; mf++) {
                uint32_t off = aRow + (uint32_t)(mf * 16) * (SRS * 2) + kb + aCol;
                LDSM4(ah[mf], uAh + off);
                LDSM4(al[mf], uAl + off);
            }
#pragma unroll
            for (int g = 0; g < 2; g++) {
                uint32_t off = bRow + (uint32_t)(g * 16) * (SRS * 2) + kb + bCol;
                uint32_t th[4], tl[4];
                LDSM4(th, uBh + off);
                LDSM4(tl, uBl + off);
                bh[2 * g][0] = th[0]; bh[2 * g][1] = th[1];
                bh[2 * g + 1][0] = th[2]; bh[2 * g + 1][1] = th[3];
                bl[2 * g][0] = tl[0]; bl[2 * g][1] = tl[1];
                bl[2 * g + 1][0] = tl[2]; bl[2 * g + 1][1] = tl[3];
            }
#pragma unroll
            for (int mf = 0; mf < MF; mf++)
#pragma unroll
                for (int nf = 0; nf < 4; nf++) {
                    MMA16816(acc[mf][nf], ah[mf], bh[nf]);
                    MMA16816(acc[mf][nf], ah[mf], bl[nf]);
                    MMA16816(acc[mf][nf], al[mf], bh[nf]);
                }
        }
        __syncthreads();
    }

    // ---- epilogue: accum regs -> gmem fp32 ----
    const int rbase = m0 + wm * MT + (lane >> 2);
    const int cbase = n0 + wn * 32 + ((lane & 3) << 1);
#pragma unroll
    for (int mf = 0; mf < MF; mf++)
#pragma unroll
        for (int nf = 0; nf < 4; nf++) {
            int r0 = rbase + mf * 16;
            int c = cbase + nf * 8;
            float2 v0 = {acc[mf][nf][0] * alpha, acc[mf][nf][1] * alpha};
            float2 v1 = {acc[mf][nf][2] * alpha, acc[mf][nf][3] * alpha};
            *(float2*)(C + (size_t)r0 * ldc + c) = v0;
            *(float2*)(C + (size_t)(r0 + 8) * ldc + c) = v1;
        }
}

// ---------------------------------------------------------------------------
// Transpose: dst[c, r] = src[r, c]
// ---------------------------------------------------------------------------
__global__ __launch_bounds__(256) void k_transpose(const float* __restrict__ src,
                                                   float* __restrict__ dst, int R, int C)
{
    __shared__ float t[32][33];
    const float* s = src + (size_t)blockIdx.z * R * C;
    float* d = dst + (size_t)blockIdx.z * R * C;
    int c0 = blockIdx.x * 32, r0 = blockIdx.y * 32;
    for (int dy = threadIdx.y; dy < 32; dy += 8)
        t[dy][threadIdx.x] = s[(size_t)(r0 + dy) * C + c0 + threadIdx.x];
    __syncthreads();
    for (int dy = threadIdx.y; dy < 32; dy += 8)
        d[(size_t)(c0 + dy) * R + r0 + threadIdx.x] = t[threadIdx.x][dy];
}

// ---------------------------------------------------------------------------
// Stage kernels
// ---------------------------------------------------------------------------
__global__ __launch_bounds__(256) void k_qkv_mma(const float* __restrict__ x)
{
    int which = blockIdx.z;
    const float* W = (which == 0) ? g_wqt : (which == 1) ? g_wkt : g_wvt;
    float* O = (which == 0) ? g_q : (which == 1) ? g_k : g_v;
    float alpha = (which == 0) ? 0.125f : 1.0f;
    hmma_gemm<128>(x, DM, W, DM, O, DM, DM, alpha, blockIdx.y * 128, blockIdx.x * 128);
}

__global__ __launch_bounds__(256) void k_scores_mma()
{
    int z = blockIdx.z, b = z >> 3, h = z & 7;
    const float* A = g_q + (size_t)b * PLEN * DM + h * DH;
    const float* B = g_k + (size_t)b * PLEN * DM + h * DH;
    float* C = g_S + (size_t)z * PLEN * PLEN;
    hmma_gemm<128>(A, DM, B, DM, C, PLEN, DH, 1.0f, blockIdx.y * 128, blockIdx.x * 128);
}

__global__ __launch_bounds__(256) void k_pv_mma()
{
    int z = blockIdx.z, b = z >> 3, g = z & 7;
    const float* A = g_S + (size_t)z * PLEN * PLEN;
    const float* B = g_vt + (size_t)b * DM * PLEN + (size_t)g * DH * PLEN;
    float* C = g_oh + (size_t)b * PLEN * DM + g * DH;
    hmma_gemm<64>(A, PLEN, B, PLEN, C, DM, PLEN, 1.0f, blockIdx.y * 128, 0);
}

__global__ __launch_bounds__(256) void k_proj_mma(float* __restrict__ out)
{
    hmma_gemm<128>(g_oh, DM, g_wpt, DM, out, DM, DM, 1.0f,
                   blockIdx.y * 128, blockIdx.x * 128);
}

// ---------------------------------------------------------------------------
// Stage 3: head-mix (W1) -> softmax -> head-mix (W2, /l folded), in place.
// ---------------------------------------------------------------------------
__device__ __forceinline__ float block_reduce_max(float v, float* red)
{
#pragma unroll
    for (int o = 16; o; o >>= 1) v = fmaxf(v, __shfl_xor_sync(0xffffffffu, v, o));
    int w = threadIdx.x >> 5;
    if ((threadIdx.x & 31) == 0) red[w] = v;
    __syncthreads();
    if (threadIdx.x < 16) {
        v = red[threadIdx.x];
#pragma unroll
        for (int o = 8; o; o >>= 1) v = fmaxf(v, __shfl_xor_sync(0xffffu, v, o));
        if (threadIdx.x == 0) red[0] = v;
    }
    __syncthreads();
    v = red[0];
    __syncthreads();
    return v;
}

__device__ __forceinline__ float block_reduce_sum(float v, float* red)
{
#pragma unroll
    for (int o = 16; o; o >>= 1) v += __shfl_xor_sync(0xffffffffu, v, o);
    int w = threadIdx.x >> 5;
    if ((threadIdx.x & 31) == 0) red[w] = v;
    __syncthreads();
    if (threadIdx.x < 16) {
        v = red[threadIdx.x];
#pragma unroll
        for (int o = 8; o; o >>= 1) v += __shfl_xor_sync(0xffffu, v, o);
        if (threadIdx.x == 0) red[0] = v;
    }
    __syncthreads();
    v = red[0];
    __syncthreads();
    return v;
}

__global__ __launch_bounds__(512) void k_mix_softmax(
    const float* __restrict__ W1, const float* __restrict__ W2)
{
    extern __shared__ float smix[];  // [8][2048]
    __shared__ float red[16];
    __shared__ float w1s[64];
    __shared__ float lstat[8];
    __shared__ float w2l[64];

    const int tid = threadIdx.x;
    const int i = blockIdx.x;
    const int b = blockIdx.y;

    if (tid < 64) w1s[tid] = W1[tid];
    __syncthreads();

    float* Srow = g_S + (size_t)b * NH * PLEN * PLEN + (size_t)i * PLEN;

#pragma unroll
    for (int j0 = 0; j0 < PLEN; j0 += 512) {
        int j = j0 + tid;
        float r[8];
#pragma unroll
        for (int h = 0; h < 8; h++) r[h] = Srow[(size_t)h * PLEN * PLEN + j];
#pragma unroll
        for (int g = 0; g < 8; g++) {
            float a = 0.f;
#pragma unroll
            for (int h = 0; h < 8; h++) a += w1s[h * 8 + g] * r[h];
            smix[g * PLEN + j] = a;
        }
    }
    __syncthreads();

    for (int g = 0; g < 8; g++) {
        float m = -1e30f;
        for (int j = tid; j < PLEN; j += 512) m = fmaxf(m, smix[g * PLEN + j]);
        m = block_reduce_max(m, red);
        float l = 0.f;
        for (int j = tid; j < PLEN; j += 512) {
            float e = __expf(smix[g * PLEN + j] - m);
            smix[g * PLEN + j] = e;
            l += e;
        }
        l = block_reduce_sum(l, red);
        if (tid == 0) lstat[g] = l;
        __syncthreads();
    }

    if (tid < 64) w2l[tid] = W2[tid] / lstat[tid >> 3];
    __syncthreads();

#pragma unroll
    for (int j0 = 0; j0 < PLEN; j0 += 512) {
        int j = j0 + tid;
        float e[8];
#pragma unroll
        for (int g = 0; g < 8; g++) e[g] = smix[g * PLEN + j];
#pragma unroll
        for (int gp = 0; gp < 8; gp++) {
            float a = 0.f;
#pragma unroll
            for (int g = 0; g < 8; g++) a += w2l[g * 8 + gp] * e[g];
            Srow[(size_t)gp * PLEN * PLEN + j] = a;
        }
    }
}

// ---------------------------------------------------------------------------
extern "C" void kernel_launch(void* const* d_in, const int* in_sizes, int n_in,
                              void* d_out, int out_size)
{
    const float* x     = (const float*)d_in[0];
    const float* Wq    = (const float*)d_in[1];
    const float* Wk    = (const float*)d_in[2];
    const float* Wv    = (const float*)d_in[3];
    const float* W1    = (const float*)d_in[4];
    const float* W2    = (const float*)d_in[5];
    const float* Wproj = (const float*)d_in[6];
    float* out = (float*)d_out;

    cudaFuncSetAttribute(k_mix_softmax, cudaFuncAttributeMaxDynamicSharedMemorySize, 65536);

    float* wqt = nullptr; cudaGetSymbolAddress((void**)&wqt, g_wqt);
    float* wkt = nullptr; cudaGetSymbolAddress((void**)&wkt, g_wkt);
    float* wvt = nullptr; cudaGetSymbolAddress((void**)&wvt, g_wvt);
    float* wpt = nullptr; cudaGetSymbolAddress((void**)&wpt, g_wpt);
    float* vp  = nullptr; cudaGetSymbolAddress((void**)&vp,  g_v);
    float* vtp = nullptr; cudaGetSymbolAddress((void**)&vtp, g_vt);

    // transpose weights to [N, K] K-major
    k_transpose<<<dim3(16, 16, 1), dim3(32, 8)>>>(Wq, wqt, DM, DM);
    k_transpose<<<dim3(16, 16, 1), dim3(32, 8)>>>(Wk, wkt, DM, DM);
    k_transpose<<<dim3(16, 16, 1), dim3(32, 8)>>>(Wv, wvt, DM, DM);
    k_transpose<<<dim3(16, 16, 1), dim3(32, 8)>>>(Wproj, wpt, DM, DM);

    k_qkv_mma<<<dim3(4, 32, 3), 256>>>(x);
    k_transpose<<<dim3(16, 64, 2), dim3(32, 8)>>>(vp, vtp, PLEN, DM);
    k_scores_mma<<<dim3(16, 16, 16), 256>>>();
    k_mix_softmax<<<dim3(2048, 2, 1), 512, 65536>>>(W1, W2);
    k_pv_mma<<<dim3(1, 16, 16), 256>>>();
    k_proj_mma<<<dim3(4, 32, 1), 256>>>(out);
}

// round 5
// speedup vs baseline: 2.2032x; 1.9070x over previous
#include <cuda_runtime.h>
#include <cuda_bf16.h>
#include <cstdint>

#define PLEN 2048
#define BATCH 2
#define NH 8
#define DH 64
#define DM 512
#define KSPLIT 4

static const size_t PSTRIDE = (size_t)BATCH * PLEN * DM;  // one pv partial buffer

// ---------------------------------------------------------------------------
// Scratch (allocation-free: __device__ globals)
// ---------------------------------------------------------------------------
__device__ float g_q[BATCH * PLEN * DM];
__device__ float g_k[BATCH * PLEN * DM];
__device__ float g_v[BATCH * PLEN * DM];
__device__ float g_ohp[KSPLIT * BATCH * PLEN * DM];   // pv split-K partials
__device__ float g_vt[BATCH * DM * PLEN];             // V^T: [b, d(512), j(2048)]
__device__ float g_wqt[DM * DM];
__device__ float g_wkt[DM * DM];
__device__ float g_wvt[DM * DM];
__device__ float g_wpt[DM * DM];
__device__ float g_S[(size_t)BATCH * NH * PLEN * PLEN];  // 268 MB scores / post-mix attn

// ---------------------------------------------------------------------------
// Warp MMA helpers (plain sm_80+ PTX: assembles for compute_103 non-'a')
// ---------------------------------------------------------------------------
__device__ __forceinline__ uint32_t smem_u32(const void* p) {
    uint32_t a;
    asm("{ .reg .u64 t; cvta.to.shared.u64 t, %1; cvt.u32.u64 %0, t; }" : "=r"(a) : "l"(p));
    return a;
}

#define LDSM4(r, addr)                                                         \
    asm volatile("ldmatrix.sync.aligned.m8n8.x4.shared.b16 {%0,%1,%2,%3}, [%4];" \
                 : "=r"((r)[0]), "=r"((r)[1]), "=r"((r)[2]), "=r"((r)[3])      \
                 : "r"(addr))

#define MMA16816(d, a, b)                                                      \
    asm volatile("mma.sync.aligned.m16n8k16.row.col.f32.bf16.bf16.f32 "        \
                 "{%0,%1,%2,%3}, {%4,%5,%6,%7}, {%8,%9}, {%0,%1,%2,%3};"       \
                 : "+f"((d)[0]), "+f"((d)[1]), "+f"((d)[2]), "+f"((d)[3])      \
                 : "r"((a)[0]), "r"((a)[1]), "r"((a)[2]), "r"((a)[3]),         \
                   "r"((b)[0]), "r"((b)[1]))

__device__ __forceinline__ void split_store(float4 v, __nv_bfloat16* hi,
                                            __nv_bfloat16* lo, int off)
{
    __nv_bfloat16 hx = __float2bfloat16_rn(v.x), hy = __float2bfloat16_rn(v.y);
    __nv_bfloat16 hz = __float2bfloat16_rn(v.z), hw = __float2bfloat16_rn(v.w);
    __nv_bfloat162 h01; h01.x = hx; h01.y = hy;
    __nv_bfloat162 h23; h23.x = hz; h23.y = hw;
    __nv_bfloat162 l01, l23;
    l01.x = __float2bfloat16_rn(v.x - __bfloat162float(hx));
    l01.y = __float2bfloat16_rn(v.y - __bfloat162float(hy));
    l23.x = __float2bfloat16_rn(v.z - __bfloat162float(hz));
    l23.y = __float2bfloat16_rn(v.w - __bfloat162float(hw));
    *(__nv_bfloat162*)(hi + off)     = h01;
    *(__nv_bfloat162*)(hi + off + 2) = h23;
    *(__nv_bfloat162*)(lo + off)     = l01;
    *(__nv_bfloat162*)(lo + off + 2) = l23;
}

// ---------------------------------------------------------------------------
// Double-buffered HMMA bf16-split NT GEMM:
//   C[M,N] = alpha * A[M,K] * B[N,K]^T   (fp32 I/O)
// CTA tile 128 x NT, K-chunk 32, 256 threads (8 warps), 2-stage smem pipeline.
// ASUM=4: A is the elementwise sum of 4 partial buffers at stride apstride.
// ---------------------------------------------------------------------------
#define KC 32
#define SRS 40  // smem row stride in bf16 elements (80 B, conflict-free ldmatrix)

template <int NT, int ASUM>
__device__ void hmma_gemm(const float* __restrict__ A, size_t apstride, int lda,
                          const float* __restrict__ B, int ldb,
                          float* __restrict__ C, int ldc,
                          int K, float alpha, int m0, int n0)
{
    constexpr int WN = (NT == 128) ? 4 : 2;
    constexpr int WM = 8 / WN;
    constexpr int MT = 128 / WM;
    constexpr int MF = MT / 16;
    constexpr int PB = NT / 32;            // B prefetch float4s per thread
    constexpr int AEL = 128 * SRS;         // bf16 elems per A array
    constexpr int BEL = NT * SRS;
    constexpr int BUFEL = 2 * AEL + 2 * BEL;

    extern __shared__ __nv_bfloat16 sm[];

    const int tid = threadIdx.x;
    const int wid = tid >> 5, lane = tid & 31;
    const int wm = wid / WN, wn = wid % WN;
    const uint32_t ubase = smem_u32(sm);

    const uint32_t aOff = (uint32_t)(wm * MT + (lane & 15)) * (SRS * 2)
                        + (uint32_t)(lane >> 4) * 16;
    const uint32_t bOff = (uint32_t)(wn * 32 + ((lane >> 4) << 3) + (lane & 7)) * (SRS * 2)
                        + (uint32_t)((lane >> 3) & 1) * 16;

    float acc[MF][4][4];
#pragma unroll
    for (int i = 0; i < MF; i++)
#pragma unroll
        for (int j = 0; j < 4; j++)
#pragma unroll
            for (int t = 0; t < 4; t++) acc[i][j][t] = 0.f;

    float4 pa[4], pb[PB];

#define LOAD_AB(k0_)                                                            \
    {                                                                           \
        _Pragma("unroll")                                                       \
        for (int u = 0; u < 4; u++) {                                           \
            int i_ = tid + u * 256;                                             \
            int r_ = i_ >> 3, c4_ = (i_ & 7) << 2;                              \
            size_t idx_ = (size_t)(m0 + r_) * lda + (k0_) + c4_;                \
            float4 v_ = *(const float4*)(A + idx_);                             \
            if (ASUM == 4) {                                                    \
                float4 v1_ = *(const float4*)(A + idx_ + apstride);             \
                float4 v2_ = *(const float4*)(A + idx_ + 2 * apstride);         \
                float4 v3_ = *(const float4*)(A + idx_ + 3 * apstride);         \
                v_.x += v1_.x + v2_.x + v3_.x;                                  \
                v_.y += v1_.y + v2_.y + v3_.y;                                  \
                v_.z += v1_.z + v2_.z + v3_.z;                                  \
                v_.w += v1_.w + v2_.w + v3_.w;                                  \
            }                                                                   \
            pa[u] = v_;                                                         \
        }                                                                       \
        _Pragma("unroll")                                                       \
        for (int u = 0; u < PB; u++) {                                          \
            int i_ = tid + u * 256;                                             \
            int r_ = i_ >> 3, c4_ = (i_ & 7) << 2;                              \
            pb[u] = *(const float4*)(B + (size_t)(n0 + r_) * ldb + (k0_) + c4_);\
        }                                                                       \
    }

#define STORE_BUF(bi_)                                                          \
    {                                                                           \
        __nv_bfloat16* Ah_ = sm + (bi_) * BUFEL;                                \
        __nv_bfloat16* Bh_ = Ah_ + AEL;                                         \
        __nv_bfloat16* Al_ = Bh_ + BEL;                                         \
        __nv_bfloat16* Bl_ = Al_ + AEL;                                         \
        _Pragma("unroll")                                                       \
        for (int u = 0; u < 4; u++) {                                           \
            int i_ = tid + u * 256;                                             \
            int r_ = i_ >> 3, c4_ = (i_ & 7) << 2;                              \
            split_store(pa[u], Ah_, Al_, r_ * SRS + c4_);                       \
        }                                                                       \
        _Pragma("unroll")                                                       \
        for (int u = 0; u < PB; u++) {                                          \
            int i_ = tid + u * 256;                                             \
            int r_ = i_ >> 3, c4_ = (i_ & 7) << 2;                              \
            split_store(pb[u], Bh_, Bl_, r_ * SRS + c4_);                       \
        }                                                                       \
    }

    LOAD_AB(0);
    STORE_BUF(0);
    __syncthreads();

    const int nch = K / KC;
    for (int ch = 0; ch < nch; ch++) {
        if (ch + 1 < nch) LOAD_AB((ch + 1) * KC);

        const uint32_t bb = (uint32_t)((ch & 1) * BUFEL * 2);
        const uint32_t uAh = ubase + bb;
        const uint32_t uBh = uAh + AEL * 2;
        const uint32_t uAl = uBh + BEL * 2;
        const uint32_t uBl = uAl + AEL * 2;

#pragma unroll
        for (int ks = 0; ks < 2; ks++) {
            const uint32_t kb = (uint32_t)(ks * 32);  // 16 bf16 = 32 bytes
            uint32_t ah[MF][4], al[MF][4], bh[4][2], bl[4][2];
#pragma unroll
            for (int mf = 0; mf < MF; mf++) {
                uint32_t off = aOff + (uint32_t)(mf * 16) * (SRS * 2) + kb;
                LDSM4(ah[mf], uAh + off);
                LDSM4(al[mf], uAl + off);
            }
#pragma unroll
            for (int g = 0; g < 2; g++) {
                uint32_t off = bOff + (uint32_t)(g * 16) * (SRS * 2) + kb;
                uint32_t th[4], tl[4];
                LDSM4(th, uBh + off);
                LDSM4(tl, uBl + off);
                bh[2 * g][0] = th[0]; bh[2 * g][1] = th[1];
                bh[2 * g + 1][0] = th[2]; bh[2 * g + 1][1] = th[3];
                bl[2 * g][0] = tl[0]; bl[2 * g][1] = tl[1];
                bl[2 * g + 1][0] = tl[2]; bl[2 * g + 1][1] = tl[3];
            }
#pragma unroll
            for (int mf = 0; mf < MF; mf++)
#pragma unroll
                for (int nf = 0; nf < 4; nf++) {
                    MMA16816(acc[mf][nf], ah[mf], bh[nf]);
                    MMA16816(acc[mf][nf], ah[mf], bl[nf]);
                    MMA16816(acc[mf][nf], al[mf], bh[nf]);
                }
        }

        if (ch + 1 < nch) {
            STORE_BUF((ch + 1) & 1);
            __syncthreads();
        }
    }

    // ---- epilogue ----
    const int rbase = m0 + wm * MT + (lane >> 2);
    const int cbase = n0 + wn * 32 + ((lane & 3) << 1);
#pragma unroll
    for (int mf = 0; mf < MF; mf++)
#pragma unroll
        for (int nf = 0; nf < 4; nf++) {
            int r0 = rbase + mf * 16;
            int c = cbase + nf * 8;
            float2 v0 = {acc[mf][nf][0] * alpha, acc[mf][nf][1] * alpha};
            float2 v1 = {acc[mf][nf][2] * alpha, acc[mf][nf][3] * alpha};
            *(float2*)(C + (size_t)r0 * ldc + c) = v0;
            *(float2*)(C + (size_t)(r0 + 8) * ldc + c) = v1;
        }
#undef LOAD_AB
#undef STORE_BUF
}

#define SMEM_G128 (2 * (2 * 128 * SRS + 2 * 128 * SRS) * 2)  // 81920 B
#define SMEM_G64  (2 * (2 * 128 * SRS + 2 * 64 * SRS) * 2)   // 61440 B

// ---------------------------------------------------------------------------
// Transpose: dst[c, r] = src[r, c]
// ---------------------------------------------------------------------------
__global__ __launch_bounds__(256) void k_transpose(const float* __restrict__ src,
                                                   float* __restrict__ dst, int R, int C)
{
    __shared__ float t[32][33];
    const float* s = src + (size_t)blockIdx.z * R * C;
    float* d = dst + (size_t)blockIdx.z * R * C;
    int c0 = blockIdx.x * 32, r0 = blockIdx.y * 32;
    for (int dy = threadIdx.y; dy < 32; dy += 8)
        t[dy][threadIdx.x] = s[(size_t)(r0 + dy) * C + c0 + threadIdx.x];
    __syncthreads();
    for (int dy = threadIdx.y; dy < 32; dy += 8)
        d[(size_t)(c0 + dy) * R + r0 + threadIdx.x] = t[threadIdx.x][dy];
}

// ---------------------------------------------------------------------------
// Stage kernels
// ---------------------------------------------------------------------------
__global__ __launch_bounds__(256) void k_qkv_mma(const float* __restrict__ x)
{
    int which = blockIdx.z;
    const float* W = (which == 0) ? g_wqt : (which == 1) ? g_wkt : g_wvt;
    float* O = (which == 0) ? g_q : (which == 1) ? g_k : g_v;
    float alpha = (which == 0) ? 0.125f : 1.0f;
    hmma_gemm<128, 1>(x, 0, DM, W, DM, O, DM, DM, alpha,
                      blockIdx.y * 128, blockIdx.x * 128);
}

__global__ __launch_bounds__(256) void k_scores_mma()
{
    int z = blockIdx.z, b = z >> 3, h = z & 7;
    const float* A = g_q + (size_t)b * PLEN * DM + h * DH;
    const float* B = g_k + (size_t)b * PLEN * DM + h * DH;
    float* C = g_S + (size_t)z * PLEN * PLEN;
    hmma_gemm<128, 1>(A, 0, DM, B, DM, C, PLEN, DH, 1.0f,
                      blockIdx.y * 128, blockIdx.x * 128);
}

__global__ __launch_bounds__(256) void k_pv_mma()
{
    int kidx = blockIdx.x;
    int z = blockIdx.z, b = z >> 3, g = z & 7;
    const float* A = g_S + (size_t)z * PLEN * PLEN + kidx * (PLEN / KSPLIT);
    const float* B = g_vt + (size_t)b * DM * PLEN + (size_t)g * DH * PLEN
                   + kidx * (PLEN / KSPLIT);
    float* C = g_ohp + (size_t)kidx * PSTRIDE + (size_t)b * PLEN * DM + g * DH;
    hmma_gemm<64, 1>(A, 0, PLEN, B, PLEN, C, DM, PLEN / KSPLIT, 1.0f,
                     blockIdx.y * 128, 0);
}

__global__ __launch_bounds__(256) void k_proj_mma(float* __restrict__ out)
{
    hmma_gemm<128, 4>(g_ohp, PSTRIDE, DM, g_wpt, DM, out, DM, DM, 1.0f,
                      blockIdx.y * 128, blockIdx.x * 128);
}

// ---------------------------------------------------------------------------
// Stage 3: head-mix (W1) -> softmax -> head-mix (W2, /l folded), in place.
// 512 thr, float4-vectorized, 2 warps per head for the softmax reductions.
// ---------------------------------------------------------------------------
__global__ __launch_bounds__(512) void k_mix_softmax(
    const float* __restrict__ W1, const float* __restrict__ W2)
{
    extern __shared__ float smix[];  // [8][2048]
    __shared__ float w1s[64], w2l[64], redm[16], reds[16];

    const int tid = threadIdx.x;
    const int i = blockIdx.x, b = blockIdx.y;

    if (tid < 64) w1s[tid] = W1[tid];
    __syncthreads();

    float* Srow = g_S + (size_t)b * NH * PLEN * PLEN + (size_t)i * PLEN;
    const int j4 = tid << 2;

    // ---- mix1 (vectorized, single pass) ----
    float4 r[8];
#pragma unroll
    for (int h = 0; h < 8; h++)
        r[h] = *(const float4*)(Srow + (size_t)h * PLEN * PLEN + j4);
#pragma unroll
    for (int g = 0; g < 8; g++) {
        float4 a = {0.f, 0.f, 0.f, 0.f};
#pragma unroll
        for (int h = 0; h < 8; h++) {
            float w = w1s[h * 8 + g];
            a.x += w * r[h].x; a.y += w * r[h].y;
            a.z += w * r[h].z; a.w += w * r[h].w;
        }
        *(float4*)(smix + g * PLEN + j4) = a;
    }
    __syncthreads();

    // ---- softmax: warp pair (2 warps) per head ----
    const int wid = tid >> 5, lane = tid & 31;
    const int g = wid >> 1;
    const int t64 = ((wid & 1) << 5) + lane;
    float* sg = smix + g * PLEN;

    float m = -1e30f;
#pragma unroll
    for (int k2 = 0; k2 < 32; k2++) m = fmaxf(m, sg[t64 + (k2 << 6)]);
#pragma unroll
    for (int o = 16; o; o >>= 1) m = fmaxf(m, __shfl_xor_sync(0xffffffffu, m, o));
    if (lane == 0) redm[wid] = m;
    __syncthreads();
    m = fmaxf(redm[g << 1], redm[(g << 1) + 1]);

    float l = 0.f;
#pragma unroll
    for (int k2 = 0; k2 < 32; k2++) {
        int idx = t64 + (k2 << 6);
        float e = __expf(sg[idx] - m);
        sg[idx] = e;
        l += e;
    }
#pragma unroll
    for (int o = 16; o; o >>= 1) l += __shfl_xor_sync(0xffffffffu, l, o);
    if (lane == 0) reds[wid] = l;
    __syncthreads();

    if (tid < 64) {
        int h = tid >> 3;
        w2l[tid] = W2[tid] / (reds[h << 1] + reds[(h << 1) + 1]);
    }
    __syncthreads();

    // ---- mix2 (vectorized) ----
#pragma unroll
    for (int h = 0; h < 8; h++) r[h] = *(const float4*)(smix + h * PLEN + j4);
#pragma unroll
    for (int gp = 0; gp < 8; gp++) {
        float4 a = {0.f, 0.f, 0.f, 0.f};
#pragma unroll
        for (int h = 0; h < 8; h++) {
            float w = w2l[h * 8 + gp];
            a.x += w * r[h].x; a.y += w * r[h].y;
            a.z += w * r[h].z; a.w += w * r[h].w;
        }
        *(float4*)(Srow + (size_t)gp * PLEN * PLEN + j4) = a;
    }
}

// ---------------------------------------------------------------------------
extern "C" void kernel_launch(void* const* d_in, const int* in_sizes, int n_in,
                              void* d_out, int out_size)
{
    const float* x     = (const float*)d_in[0];
    const float* Wq    = (const float*)d_in[1];
    const float* Wk    = (const float*)d_in[2];
    const float* Wv    = (const float*)d_in[3];
    const float* W1    = (const float*)d_in[4];
    const float* W2    = (const float*)d_in[5];
    const float* Wproj = (const float*)d_in[6];
    float* out = (float*)d_out;

    cudaFuncSetAttribute(k_mix_softmax, cudaFuncAttributeMaxDynamicSharedMemorySize, 65536);
    cudaFuncSetAttribute(k_qkv_mma,    cudaFuncAttributeMaxDynamicSharedMemorySize, SMEM_G128);
    cudaFuncSetAttribute(k_scores_mma, cudaFuncAttributeMaxDynamicSharedMemorySize, SMEM_G128);
    cudaFuncSetAttribute(k_pv_mma,     cudaFuncAttributeMaxDynamicSharedMemorySize, SMEM_G64);
    cudaFuncSetAttribute(k_proj_mma,   cudaFuncAttributeMaxDynamicSharedMemorySize, SMEM_G128);

    float* wqt = nullptr; cudaGetSymbolAddress((void**)&wqt, g_wqt);
    float* wkt = nullptr; cudaGetSymbolAddress((void**)&wkt, g_wkt);
    float* wvt = nullptr; cudaGetSymbolAddress((void**)&wvt, g_wvt);
    float* wpt = nullptr; cudaGetSymbolAddress((void**)&wpt, g_wpt);
    float* vp  = nullptr; cudaGetSymbolAddress((void**)&vp,  g_v);
    float* vtp = nullptr; cudaGetSymbolAddress((void**)&vtp, g_vt);

    k_transpose<<<dim3(16, 16, 1), dim3(32, 8)>>>(Wq, wqt, DM, DM);
    k_transpose<<<dim3(16, 16, 1), dim3(32, 8)>>>(Wk, wkt, DM, DM);
    k_transpose<<<dim3(16, 16, 1), dim3(32, 8)>>>(Wv, wvt, DM, DM);
    k_transpose<<<dim3(16, 16, 1), dim3(32, 8)>>>(Wproj, wpt, DM, DM);

    k_qkv_mma<<<dim3(4, 32, 3), 256, SMEM_G128>>>(x);
    k_transpose<<<dim3(16, 64, 2), dim3(32, 8)>>>(vp, vtp, PLEN, DM);
    k_scores_mma<<<dim3(16, 16, 16), 256, SMEM_G128>>>();
    k_mix_softmax<<<dim3(2048, 2, 1), 512, 65536>>>(W1, W2);
    k_pv_mma<<<dim3(KSPLIT, 16, 16), 256, SMEM_G64>>>();
    k_proj_mma<<<dim3(4, 32, 1), 256, SMEM_G128>>>(out);
}

// round 8
// speedup vs baseline: 2.3839x; 1.0820x over previous
#include <cuda_runtime.h>
#include <cuda_bf16.h>
#include <cuda_fp16.h>
#include <cstdint>

#define PLEN 2048
#define BATCH 2
#define NH 8
#define DH 64
#define DM 512
#define KSPLIT 4

static const size_t PSTRIDE = (size_t)BATCH * PLEN * DM;  // one pv partial buffer

// ---------------------------------------------------------------------------
// Scratch (allocation-free: __device__ globals)
// ---------------------------------------------------------------------------
__device__ float g_q[BATCH * PLEN * DM];
__device__ float g_k[BATCH * PLEN * DM];
__device__ float g_v[BATCH * PLEN * DM];
__device__ float g_ohp[KSPLIT * BATCH * PLEN * DM];   // pv split-K partials
__device__ float g_vt[BATCH * DM * PLEN];             // V^T: [b, d(512), j(2048)]
__device__ float g_wqt[DM * DM];
__device__ float g_wkt[DM * DM];
__device__ float g_wvt[DM * DM];
__device__ float g_wpt[DM * DM];
__device__ float g_S[(size_t)BATCH * NH * PLEN * PLEN];       // 268 MB fp32 raw scores
__device__ __half g_Sh[(size_t)BATCH * NH * PLEN * PLEN];     // 134 MB fp16 post-mix attn

// ---------------------------------------------------------------------------
// Warp MMA helpers (plain sm_80+ PTX: assembles for compute_103 non-'a')
// ---------------------------------------------------------------------------
__device__ __forceinline__ uint32_t smem_u32(const void* p) {
    uint32_t a;
    asm("{ .reg .u64 t; cvta.to.shared.u64 t, %1; cvt.u32.u64 %0, t; }" : "=r"(a) : "l"(p));
    return a;
}

#define LDSM4(r, addr)                                                         \
    asm volatile("ldmatrix.sync.aligned.m8n8.x4.shared.b16 {%0,%1,%2,%3}, [%4];" \
                 : "=r"((r)[0]), "=r"((r)[1]), "=r"((r)[2]), "=r"((r)[3])      \
                 : "r"(addr))

#define MMA16816(d, a, b)                                                      \
    asm volatile("mma.sync.aligned.m16n8k16.row.col.f32.bf16.bf16.f32 "        \
                 "{%0,%1,%2,%3}, {%4,%5,%6,%7}, {%8,%9}, {%0,%1,%2,%3};"       \
                 : "+f"((d)[0]), "+f"((d)[1]), "+f"((d)[2]), "+f"((d)[3])      \
                 : "r"((a)[0]), "r"((a)[1]), "r"((a)[2]), "r"((a)[3]),         \
                   "r"((b)[0]), "r"((b)[1]))

#define MMA16816H(d, a, b)                                                     \
    asm volatile("mma.sync.aligned.m16n8k16.row.col.f32.f16.f16.f32 "          \
                 "{%0,%1,%2,%3}, {%4,%5,%6,%7}, {%8,%9}, {%0,%1,%2,%3};"       \
                 : "+f"((d)[0]), "+f"((d)[1]), "+f"((d)[2]), "+f"((d)[3])      \
                 : "r"((a)[0]), "r"((a)[1]), "r"((a)[2]), "r"((a)[3]),         \
                   "r"((b)[0]), "r"((b)[1]))

__device__ __forceinline__ void split_store(float4 v, __nv_bfloat16* hi,
                                            __nv_bfloat16* lo, int off)
{
    __nv_bfloat16 hx = __float2bfloat16_rn(v.x), hy = __float2bfloat16_rn(v.y);
    __nv_bfloat16 hz = __float2bfloat16_rn(v.z), hw = __float2bfloat16_rn(v.w);
    __nv_bfloat162 h01; h01.x = hx; h01.y = hy;
    __nv_bfloat162 h23; h23.x = hz; h23.y = hw;
    __nv_bfloat162 l01, l23;
    l01.x = __float2bfloat16_rn(v.x - __bfloat162float(hx));
    l01.y = __float2bfloat16_rn(v.y - __bfloat162float(hy));
    l23.x = __float2bfloat16_rn(v.z - __bfloat162float(hz));
    l23.y = __float2bfloat16_rn(v.w - __bfloat162float(hw));
    *(__nv_bfloat162*)(hi + off)     = h01;
    *(__nv_bfloat162*)(hi + off + 2) = h23;
    *(__nv_bfloat162*)(lo + off)     = l01;
    *(__nv_bfloat162*)(lo + off + 2) = l23;
}

// fp16 variant for the pv V operand
__device__ __forceinline__ void split_store_h(float4 v, __half* hi,
                                              __half* lo, int off)
{
    __half hx = __float2half_rn(v.x), hy = __float2half_rn(v.y);
    __half hz = __float2half_rn(v.z), hw = __float2half_rn(v.w);
    __half2 h01; h01.x = hx; h01.y = hy;
    __half2 h23; h23.x = hz; h23.y = hw;
    __half2 l01, l23;
    l01.x = __float2half_rn(v.x - __half2float(hx));
    l01.y = __float2half_rn(v.y - __half2float(hy));
    l23.x = __float2half_rn(v.z - __half2float(hz));
    l23.y = __float2half_rn(v.w - __half2float(hw));
    *(__half2*)(hi + off)     = h01;
    *(__half2*)(hi + off + 2) = h23;
    *(__half2*)(lo + off)     = l01;
    *(__half2*)(lo + off + 2) = l23;
}

// ---------------------------------------------------------------------------
// Double-buffered HMMA bf16-split NT GEMM:
//   C[M,N] = alpha * A[M,K] * B[N,K]^T   (fp32 I/O)
// CTA tile 128 x NT, K-chunk 32, 256 threads (8 warps), 2-stage smem pipeline.
// ASUM=4: A is the elementwise sum of 4 partial buffers at stride apstride.
// ---------------------------------------------------------------------------
#define KC 32
#define SRS 40  // smem row stride in bf16 elements (80 B)

template <int NT, int ASUM>
__device__ void hmma_gemm(const float* __restrict__ A, size_t apstride, int lda,
                          const float* __restrict__ B, int ldb,
                          float* __restrict__ C, int ldc,
                          int K, float alpha, int m0, int n0)
{
    constexpr int WN = (NT == 128) ? 4 : 2;
    constexpr int WM = 8 / WN;
    constexpr int MT = 128 / WM;
    constexpr int MF = MT / 16;
    constexpr int PB = NT / 32;
    constexpr int AEL = 128 * SRS;
    constexpr int BEL = NT * SRS;
    constexpr int BUFEL = 2 * AEL + 2 * BEL;

    extern __shared__ __nv_bfloat16 sm[];

    const int tid = threadIdx.x;
    const int wid = tid >> 5, lane = tid & 31;
    const int wm = wid / WN, wn = wid % WN;
    const uint32_t ubase = smem_u32(sm);

    const uint32_t aOff = (uint32_t)(wm * MT + (lane & 15)) * (SRS * 2)
                        + (uint32_t)(lane >> 4) * 16;
    const uint32_t bOff = (uint32_t)(wn * 32 + ((lane >> 4) << 3) + (lane & 7)) * (SRS * 2)
                        + (uint32_t)((lane >> 3) & 1) * 16;

    float acc[MF][4][4];
#pragma unroll
    for (int i = 0; i < MF; i++)
#pragma unroll
        for (int j = 0; j < 4; j++)
#pragma unroll
            for (int t = 0; t < 4; t++) acc[i][j][t] = 0.f;

    float4 pa[4], pb[PB];

#define LOAD_AB(k0_)                                                            \
    {                                                                           \
        _Pragma("unroll")                                                       \
        for (int u = 0; u < 4; u++) {                                           \
            int i_ = tid + u * 256;                                             \
            int r_ = i_ >> 3, c4_ = (i_ & 7) << 2;                              \
            size_t idx_ = (size_t)(m0 + r_) * lda + (k0_) + c4_;                \
            float4 v_ = *(const float4*)(A + idx_);                             \
            if (ASUM == 4) {                                                    \
                float4 v1_ = *(const float4*)(A + idx_ + apstride);             \
                float4 v2_ = *(const float4*)(A + idx_ + 2 * apstride);         \
                float4 v3_ = *(const float4*)(A + idx_ + 3 * apstride);         \
                v_.x += v1_.x + v2_.x + v3_.x;                                  \
                v_.y += v1_.y + v2_.y + v3_.y;                                  \
                v_.z += v1_.z + v2_.z + v3_.z;                                  \
                v_.w += v1_.w + v2_.w + v3_.w;                                  \
            }                                                                   \
            pa[u] = v_;                                                         \
        }                                                                       \
        _Pragma("unroll")                                                       \
        for (int u = 0; u < PB; u++) {                                          \
            int i_ = tid + u * 256;                                             \
            int r_ = i_ >> 3, c4_ = (i_ & 7) << 2;                              \
            pb[u] = *(const float4*)(B + (size_t)(n0 + r_) * ldb + (k0_) + c4_);\
        }                                                                       \
    }

#define STORE_BUF(bi_)                                                          \
    {                                                                           \
        __nv_bfloat16* Ah_ = sm + (bi_) * BUFEL;                                \
        __nv_bfloat16* Bh_ = Ah_ + AEL;                                         \
        __nv_bfloat16* Al_ = Bh_ + BEL;                                         \
        __nv_bfloat16* Bl_ = Al_ + AEL;                                         \
        _Pragma("unroll")                                                       \
        for (int u = 0; u < 4; u++) {                                           \
            int i_ = tid + u * 256;                                             \
            int r_ = i_ >> 3, c4_ = (i_ & 7) << 2;                              \
            split_store(pa[u], Ah_, Al_, r_ * SRS + c4_);                       \
        }                                                                       \
        _Pragma("unroll")                                                       \
        for (int u = 0; u < PB; u++) {                                          \
            int i_ = tid + u * 256;                                             \
            int r_ = i_ >> 3, c4_ = (i_ & 7) << 2;                              \
            split_store(pb[u], Bh_, Bl_, r_ * SRS + c4_);                       \
        }                                                                       \
    }

    LOAD_AB(0);
    STORE_BUF(0);
    __syncthreads();

    const int nch = K / KC;
    for (int ch = 0; ch < nch; ch++) {
        if (ch + 1 < nch) LOAD_AB((ch + 1) * KC);

        const uint32_t bb = (uint32_t)((ch & 1) * BUFEL * 2);
        const uint32_t uAh = ubase + bb;
        const uint32_t uBh = uAh + AEL * 2;
        const uint32_t uAl = uBh + BEL * 2;
        const uint32_t uBl = uAl + AEL * 2;

#pragma unroll
        for (int ks = 0; ks < 2; ks++) {
            const uint32_t kb = (uint32_t)(ks * 32);
            uint32_t ah[MF][4], al[MF][4], bh[4][2], bl[4][2];
#pragma unroll
            for (int mf = 0; mf < MF; mf++) {
                uint32_t off = aOff + (uint32_t)(mf * 16) * (SRS * 2) + kb;
                LDSM4(ah[mf], uAh + off);
                LDSM4(al[mf], uAl + off);
            }
#pragma unroll
            for (int g = 0; g < 2; g++) {
                uint32_t off = bOff + (uint32_t)(g * 16) * (SRS * 2) + kb;
                uint32_t th[4], tl[4];
                LDSM4(th, uBh + off);
                LDSM4(tl, uBl + off);
                bh[2 * g][0] = th[0]; bh[2 * g][1] = th[1];
                bh[2 * g + 1][0] = th[2]; bh[2 * g + 1][1] = th[3];
                bl[2 * g][0] = tl[0]; bl[2 * g][1] = tl[1];
                bl[2 * g + 1][0] = tl[2]; bl[2 * g + 1][1] = tl[3];
            }
#pragma unroll
            for (int mf = 0; mf < MF; mf++)
#pragma unroll
                for (int nf = 0; nf < 4; nf++) {
                    MMA16816(acc[mf][nf], ah[mf], bh[nf]);
                    MMA16816(acc[mf][nf], ah[mf], bl[nf]);
                    MMA16816(acc[mf][nf], al[mf], bh[nf]);
                }
        }

        if (ch + 1 < nch) {
            STORE_BUF((ch + 1) & 1);
            __syncthreads();
        }
    }

    // ---- epilogue ----
    const int rbase = m0 + wm * MT + (lane >> 2);
    const int cbase = n0 + wn * 32 + ((lane & 3) << 1);
#pragma unroll
    for (int mf = 0; mf < MF; mf++)
#pragma unroll
        for (int nf = 0; nf < 4; nf++) {
            int r0 = rbase + mf * 16;
            int c = cbase + nf * 8;
            float2 v0 = {acc[mf][nf][0] * alpha, acc[mf][nf][1] * alpha};
            float2 v1 = {acc[mf][nf][2] * alpha, acc[mf][nf][3] * alpha};
            *(float2*)(C + (size_t)r0 * ldc + c) = v0;
            *(float2*)(C + (size_t)(r0 + 8) * ldc + c) = v1;
        }
#undef LOAD_AB
#undef STORE_BUF
}

#define SMEM_G128 (2 * (2 * 128 * SRS + 2 * 128 * SRS) * 2)  // 81920 B

// ---------------------------------------------------------------------------
// pv GEMM: A fp16 (direct copy), B fp32 split to f16 hi/lo. NT=64, 2-term MMA.
//   C[M,64] = A[M,K](f16) * B[64,K]^T
// ---------------------------------------------------------------------------
template <int DUMMY>
__device__ void hmma_gemm_hA(const __half* __restrict__ A, int lda,
                             const float* __restrict__ B, int ldb,
                             float* __restrict__ C, int ldc,
                             int K, int m0)
{
    constexpr int NT = 64, WN = 2, MT = 32, MF = 2;
    constexpr int AEL = 128 * SRS;
    constexpr int BEL = NT * SRS;
    constexpr int BUFEL = AEL + 2 * BEL;

    extern __shared__ __nv_bfloat16 smb[];
    __half* sm = (__half*)smb;

    const int tid = threadIdx.x;
    const int wid = tid >> 5, lane = tid & 31;
    const int wm = wid / WN, wn = wid % WN;
    const uint32_t ubase = smem_u32(sm);

    const uint32_t aOff = (uint32_t)(wm * MT + (lane & 15)) * (SRS * 2)
                        + (uint32_t)(lane >> 4) * 16;
    const uint32_t bOff = (uint32_t)(wn * 32 + ((lane >> 4) << 3) + (lane & 7)) * (SRS * 2)
                        + (uint32_t)((lane >> 3) & 1) * 16;

    float acc[MF][4][4];
#pragma unroll
    for (int i = 0; i < MF; i++)
#pragma unroll
        for (int j = 0; j < 4; j++)
#pragma unroll
            for (int t = 0; t < 4; t++) acc[i][j][t] = 0.f;

    uint2 pa[4];
    float4 pb[2];

#define LOAD_AB2(k0_)                                                           \
    {                                                                           \
        _Pragma("unroll")                                                       \
        for (int u = 0; u < 4; u++) {                                           \
            int i_ = tid + u * 256;                                             \
            int r_ = i_ >> 3, c4_ = (i_ & 7) << 2;                              \
            pa[u] = *(const uint2*)(A + (size_t)(m0 + r_) * lda + (k0_) + c4_); \
        }                                                                       \
        _Pragma("unroll")                                                       \
        for (int u = 0; u < 2; u++) {                                           \
            int i_ = tid + u * 256;                                             \
            int r_ = i_ >> 3, c4_ = (i_ & 7) << 2;                              \
            pb[u] = *(const float4*)(B + (size_t)r_ * ldb + (k0_) + c4_);       \
        }                                                                       \
    }

#define STORE_BUF2(bi_)                                                         \
    {                                                                           \
        __half* Ah_ = sm + (bi_) * BUFEL;                                       \
        __half* Bh_ = Ah_ + AEL;                                                \
        __half* Bl_ = Bh_ + BEL;                                                \
        _Pragma("unroll")                                                       \
        for (int u = 0; u < 4; u++) {                                           \
            int i_ = tid + u * 256;                                             \
            int r_ = i_ >> 3, c4_ = (i_ & 7) << 2;                              \
            *(uint2*)(Ah_ + r_ * SRS + c4_) = pa[u];                            \
        }                                                                       \
        _Pragma("unroll")                                                       \
        for (int u = 0; u < 2; u++) {                                           \
            int i_ = tid + u * 256;                                             \
            int r_ = i_ >> 3, c4_ = (i_ & 7) << 2;                              \
            split_store_h(pb[u], Bh_, Bl_, r_ * SRS + c4_);                     \
        }                                                                       \
    }

    LOAD_AB2(0);
    STORE_BUF2(0);
    __syncthreads();

    const int nch = K / KC;
    for (int ch = 0; ch < nch; ch++) {
        if (ch + 1 < nch) LOAD_AB2((ch + 1) * KC);

        const uint32_t bb = (uint32_t)((ch & 1) * BUFEL * 2);
        const uint32_t uAh = ubase + bb;
        const uint32_t uBh = uAh + AEL * 2;
        const uint32_t uBl = uBh + BEL * 2;

#pragma unroll
        for (int ks = 0; ks < 2; ks++) {
            const uint32_t kb = (uint32_t)(ks * 32);
            uint32_t ah[MF][4], bh[4][2], bl[4][2];
#pragma unroll
            for (int mf = 0; mf < MF; mf++) {
                uint32_t off = aOff + (uint32_t)(mf * 16) * (SRS * 2) + kb;
                LDSM4(ah[mf], uAh + off);
            }
#pragma unroll
            for (int g = 0; g < 2; g++) {
                uint32_t off = bOff + (uint32_t)(g * 16) * (SRS * 2) + kb;
                uint32_t th[4], tl[4];
                LDSM4(th, uBh + off);
                LDSM4(tl, uBl + off);
                bh[2 * g][0] = th[0]; bh[2 * g][1] = th[1];
                bh[2 * g + 1][0] = th[2]; bh[2 * g + 1][1] = th[3];
                bl[2 * g][0] = tl[0]; bl[2 * g][1] = tl[1];
                bl[2 * g + 1][0] = tl[2]; bl[2 * g + 1][1] = tl[3];
            }
#pragma unroll
            for (int mf = 0; mf < MF; mf++)
#pragma unroll
                for (int nf = 0; nf < 4; nf++) {
                    MMA16816H(acc[mf][nf], ah[mf], bh[nf]);
                    MMA16816H(acc[mf][nf], ah[mf], bl[nf]);
                }
        }

        if (ch + 1 < nch) {
            STORE_BUF2((ch + 1) & 1);
            __syncthreads();
        }
    }

    const int rbase = m0 + wm * MT + (lane >> 2);
    const int cbase = wn * 32 + ((lane & 3) << 1);
#pragma unroll
    for (int mf = 0; mf < MF; mf++)
#pragma unroll
        for (int nf = 0; nf < 4; nf++) {
            int r0 = rbase + mf * 16;
            int c = cbase + nf * 8;
            float2 v0 = {acc[mf][nf][0], acc[mf][nf][1]};
            float2 v1 = {acc[mf][nf][2], acc[mf][nf][3]};
            *(float2*)(C + (size_t)r0 * ldc + c) = v0;
            *(float2*)(C + (size_t)(r0 + 8) * ldc + c) = v1;
        }
#undef LOAD_AB2
#undef STORE_BUF2
}

#define SMEM_PV (2 * (128 * SRS + 2 * 64 * SRS) * 2)  // 40960 B

// ---------------------------------------------------------------------------
// Transpose: dst[c, r] = src[r, c]
// ---------------------------------------------------------------------------
__global__ __launch_bounds__(256) void k_transpose(const float* __restrict__ src,
                                                   float* __restrict__ dst, int R, int C)
{
    __shared__ float t[32][33];
    const float* s = src + (size_t)blockIdx.z * R * C;
    float* d = dst + (size_t)blockIdx.z * R * C;
    int c0 = blockIdx.x * 32, r0 = blockIdx.y * 32;
    for (int dy = threadIdx.y; dy < 32; dy += 8)
        t[dy][threadIdx.x] = s[(size_t)(r0 + dy) * C + c0 + threadIdx.x];
    __syncthreads();
    for (int dy = threadIdx.y; dy < 32; dy += 8)
        d[(size_t)(c0 + dy) * R + r0 + threadIdx.x] = t[threadIdx.x][dy];
}

// ---------------------------------------------------------------------------
// Stage kernels
// ---------------------------------------------------------------------------
__global__ __launch_bounds__(256) void k_qkv_mma(const float* __restrict__ x)
{
    int which = blockIdx.z;
    const float* W = (which == 0) ? g_wqt : (which == 1) ? g_wkt : g_wvt;
    float* O = (which == 0) ? g_q : (which == 1) ? g_k : g_v;
    float alpha = (which == 0) ? 0.125f : 1.0f;
    hmma_gemm<128, 1>(x, 0, DM, W, DM, O, DM, DM, alpha,
                      blockIdx.y * 128, blockIdx.x * 128);
}

__global__ __launch_bounds__(256) void k_scores_mma()
{
    int z = blockIdx.z, b = z >> 3, h = z & 7;
    const float* A = g_q + (size_t)b * PLEN * DM + h * DH;
    const float* B = g_k + (size_t)b * PLEN * DM + h * DH;
    float* C = g_S + (size_t)z * PLEN * PLEN;
    hmma_gemm<128, 1>(A, 0, DM, B, DM, C, PLEN, DH, 1.0f,
                      blockIdx.y * 128, blockIdx.x * 128);
}

__global__ __launch_bounds__(256) void k_pv_mma()
{
    int kidx = blockIdx.x;
    int z = blockIdx.z, b = z >> 3, g = z & 7;
    const __half* A = g_Sh + (size_t)z * PLEN * PLEN + kidx * (PLEN / KSPLIT);
    const float* B = g_vt + (size_t)b * DM * PLEN + (size_t)g * DH * PLEN
                   + kidx * (PLEN / KSPLIT);
    float* C = g_ohp + (size_t)kidx * PSTRIDE + (size_t)b * PLEN * DM + g * DH;
    hmma_gemm_hA<0>(A, PLEN, B, PLEN, C, DM, PLEN / KSPLIT, blockIdx.y * 128);
}

__global__ __launch_bounds__(256) void k_proj_mma(float* __restrict__ out)
{
    hmma_gemm<128, 4>(g_ohp, PSTRIDE, DM, g_wpt, DM, out, DM, DM, 1.0f,
                      blockIdx.y * 128, blockIdx.x * 128);
}

// ---------------------------------------------------------------------------
// Stage 3: head-mix (W1) -> softmax -> head-mix (W2, /l folded).
// Reads fp32 g_S, writes fp16 g_Sh. 512 thr, 2 warps per head.
// ---------------------------------------------------------------------------
__device__ __forceinline__ void st4h(__half* p, float4 v) {
    __half2 a, b;
    a.x = __float2half_rn(v.x); a.y = __float2half_rn(v.y);
    b.x = __float2half_rn(v.z); b.y = __float2half_rn(v.w);
    uint2 u;
    u.x = *(uint32_t*)&a; u.y = *(uint32_t*)&b;
    *(uint2*)p = u;
}

__global__ __launch_bounds__(512) void k_mix_softmax(
    const float* __restrict__ W1, const float* __restrict__ W2)
{
    extern __shared__ float smix[];  // [8][2048]
    __shared__ float w1s[64], w2l[64], redm[16], reds[16];

    const int tid = threadIdx.x;
    const int i = blockIdx.x, b = blockIdx.y;

    if (tid < 64) w1s[tid] = W1[tid];
    __syncthreads();

    const float* Srow = g_S + (size_t)b * NH * PLEN * PLEN + (size_t)i * PLEN;
    __half* Orow = g_Sh + (size_t)b * NH * PLEN * PLEN + (size_t)i * PLEN;
    const int j4 = tid << 2;

    // ---- mix1 ----
    float4 r[8];
#pragma unroll
    for (int h = 0; h < 8; h++)
        r[h] = *(const float4*)(Srow + (size_t)h * PLEN * PLEN + j4);
#pragma unroll
    for (int g = 0; g < 8; g++) {
        float4 a = {0.f, 0.f, 0.f, 0.f};
#pragma unroll
        for (int h = 0; h < 8; h++) {
            float w = w1s[h * 8 + g];
            a.x += w * r[h].x; a.y += w * r[h].y;
            a.z += w * r[h].z; a.w += w * r[h].w;
        }
        *(float4*)(smix + g * PLEN + j4) = a;
    }
    __syncthreads();

    // ---- softmax: 2 warps per head ----
    const int wid = tid >> 5, lane = tid & 31;
    const int g = wid >> 1;
    const int t64 = ((wid & 1) << 5) + lane;
    float* sg = smix + g * PLEN;

    float m = -1e30f;
#pragma unroll
    for (int k2 = 0; k2 < 32; k2++) m = fmaxf(m, sg[t64 + (k2 << 6)]);
#pragma unroll
    for (int o = 16; o; o >>= 1) m = fmaxf(m, __shfl_xor_sync(0xffffffffu, m, o));
    if (lane == 0) redm[wid] = m;
    __syncthreads();
    m = fmaxf(redm[g << 1], redm[(g << 1) + 1]);

    float l = 0.f;
#pragma unroll
    for (int k2 = 0; k2 < 32; k2++) {
        int idx = t64 + (k2 << 6);
        float e = __expf(sg[idx] - m);
        sg[idx] = e;
        l += e;
    }
#pragma unroll
    for (int o = 16; o; o >>= 1) l += __shfl_xor_sync(0xffffffffu, l, o);
    if (lane == 0) reds[wid] = l;
    __syncthreads();

    if (tid < 64) {
        int h = tid >> 3;
        w2l[tid] = W2[tid] / (reds[h << 1] + reds[(h << 1) + 1]);
    }
    __syncthreads();

    // ---- mix2 -> fp16 out ----
#pragma unroll
    for (int h = 0; h < 8; h++) r[h] = *(const float4*)(smix + h * PLEN + j4);
#pragma unroll
    for (int gp = 0; gp < 8; gp++) {
        float4 a = {0.f, 0.f, 0.f, 0.f};
#pragma unroll
        for (int h = 0; h < 8; h++) {
            float w = w2l[h * 8 + gp];
            a.x += w * r[h].x; a.y += w * r[h].y;
            a.z += w * r[h].z; a.w += w * r[h].w;
        }
        st4h(Orow + (size_t)gp * PLEN * PLEN + j4, a);
    }
}

// ---------------------------------------------------------------------------
extern "C" void kernel_launch(void* const* d_in, const int* in_sizes, int n_in,
                              void* d_out, int out_size)
{
    const float* x     = (const float*)d_in[0];
    const float* Wq    = (const float*)d_in[1];
    const float* Wk    = (const float*)d_in[2];
    const float* Wv    = (const float*)d_in[3];
    const float* W1    = (const float*)d_in[4];
    const float* W2    = (const float*)d_in[5];
    const float* Wproj = (const float*)d_in[6];
    float* out = (float*)d_out;

    cudaFuncSetAttribute(k_mix_softmax, cudaFuncAttributeMaxDynamicSharedMemorySize, 65536);
    cudaFuncSetAttribute(k_qkv_mma,    cudaFuncAttributeMaxDynamicSharedMemorySize, SMEM_G128);
    cudaFuncSetAttribute(k_scores_mma, cudaFuncAttributeMaxDynamicSharedMemorySize, SMEM_G128);
    cudaFuncSetAttribute(k_pv_mma,     cudaFuncAttributeMaxDynamicSharedMemorySize, SMEM_PV);
    cudaFuncSetAttribute(k_proj_mma,   cudaFuncAttributeMaxDynamicSharedMemorySize, SMEM_G128);

    float* wqt = nullptr; cudaGetSymbolAddress((void**)&wqt, g_wqt);
    float* wkt = nullptr; cudaGetSymbolAddress((void**)&wkt, g_wkt);
    float* wvt = nullptr; cudaGetSymbolAddress((void**)&wvt, g_wvt);
    float* wpt = nullptr; cudaGetSymbolAddress((void**)&wpt, g_wpt);
    float* vp  = nullptr; cudaGetSymbolAddress((void**)&vp,  g_v);
    float* vtp = nullptr; cudaGetSymbolAddress((void**)&vtp, g_vt);

    k_transpose<<<dim3(16, 16, 1), dim3(32, 8)>>>(Wq, wqt, DM, DM);
    k_transpose<<<dim3(16, 16, 1), dim3(32, 8)>>>(Wk, wkt, DM, DM);
    k_transpose<<<dim3(16, 16, 1), dim3(32, 8)>>>(Wv, wvt, DM, DM);
    k_transpose<<<dim3(16, 16, 1), dim3(32, 8)>>>(Wproj, wpt, DM, DM);

    k_qkv_mma<<<dim3(4, 32, 3), 256, SMEM_G128>>>(x);
    k_transpose<<<dim3(16, 64, 2), dim3(32, 8)>>>(vp, vtp, PLEN, DM);
    k_scores_mma<<<dim3(16, 16, 16), 256, SMEM_G128>>>();
    k_mix_softmax<<<dim3(2048, 2, 1), 512, 65536>>>(W1, W2);
    k_pv_mma<<<dim3(KSPLIT, 16, 16), 256, SMEM_PV>>>();
    k_proj_mma<<<dim3(4, 32, 1), 256, SMEM_G128>>>(out);
}

// round 9
// speedup vs baseline: 2.4382x; 1.0228x over previous
#include <cuda_runtime.h>
#include <cuda_bf16.h>
#include <cuda_fp16.h>
#include <cstdint>

#define PLEN 2048
#define BATCH 2
#define NH 8
#define DH 64
#define DM 512
#define KSPLIT 4

static const size_t PSTRIDE = (size_t)BATCH * PLEN * DM;  // one pv partial buffer

// ---------------------------------------------------------------------------
// Scratch (allocation-free: __device__ globals)
// ---------------------------------------------------------------------------
__device__ float g_q[BATCH * PLEN * DM];
__device__ float g_k[BATCH * PLEN * DM];
__device__ float g_v[BATCH * PLEN * DM];
__device__ float g_ohp[KSPLIT * BATCH * PLEN * DM];   // pv split-K partials
__device__ float g_vt[BATCH * DM * PLEN];             // V^T: [b, d(512), j(2048)]
__device__ float g_wqt[DM * DM];
__device__ float g_wkt[DM * DM];
__device__ float g_wvt[DM * DM];
__device__ float g_wpt[DM * DM];
__device__ __half g_S[(size_t)BATCH * NH * PLEN * PLEN];      // 134 MB fp16 raw logits
__device__ __half g_Sh[(size_t)BATCH * NH * PLEN * PLEN];     // 134 MB fp16 post-mix attn

// ---------------------------------------------------------------------------
// Warp MMA helpers (plain sm_80+ PTX: assembles for compute_103 non-'a')
// ---------------------------------------------------------------------------
__device__ __forceinline__ uint32_t smem_u32(const void* p) {
    uint32_t a;
    asm("{ .reg .u64 t; cvta.to.shared.u64 t, %1; cvt.u32.u64 %0, t; }" : "=r"(a) : "l"(p));
    return a;
}

#define LDSM4(r, addr)                                                         \
    asm volatile("ldmatrix.sync.aligned.m8n8.x4.shared.b16 {%0,%1,%2,%3}, [%4];" \
                 : "=r"((r)[0]), "=r"((r)[1]), "=r"((r)[2]), "=r"((r)[3])      \
                 : "r"(addr))

#define MMA16816(d, a, b)                                                      \
    asm volatile("mma.sync.aligned.m16n8k16.row.col.f32.bf16.bf16.f32 "        \
                 "{%0,%1,%2,%3}, {%4,%5,%6,%7}, {%8,%9}, {%0,%1,%2,%3};"       \
                 : "+f"((d)[0]), "+f"((d)[1]), "+f"((d)[2]), "+f"((d)[3])      \
                 : "r"((a)[0]), "r"((a)[1]), "r"((a)[2]), "r"((a)[3]),         \
                   "r"((b)[0]), "r"((b)[1]))

#define MMA16816H(d, a, b)                                                     \
    asm volatile("mma.sync.aligned.m16n8k16.row.col.f32.f16.f16.f32 "          \
                 "{%0,%1,%2,%3}, {%4,%5,%6,%7}, {%8,%9}, {%0,%1,%2,%3};"       \
                 : "+f"((d)[0]), "+f"((d)[1]), "+f"((d)[2]), "+f"((d)[3])      \
                 : "r"((a)[0]), "r"((a)[1]), "r"((a)[2]), "r"((a)[3]),         \
                   "r"((b)[0]), "r"((b)[1]))

__device__ __forceinline__ void split_store(float4 v, __nv_bfloat16* hi,
                                            __nv_bfloat16* lo, int off)
{
    __nv_bfloat16 hx = __float2bfloat16_rn(v.x), hy = __float2bfloat16_rn(v.y);
    __nv_bfloat16 hz = __float2bfloat16_rn(v.z), hw = __float2bfloat16_rn(v.w);
    __nv_bfloat162 h01; h01.x = hx; h01.y = hy;
    __nv_bfloat162 h23; h23.x = hz; h23.y = hw;
    __nv_bfloat162 l01, l23;
    l01.x = __float2bfloat16_rn(v.x - __bfloat162float(hx));
    l01.y = __float2bfloat16_rn(v.y - __bfloat162float(hy));
    l23.x = __float2bfloat16_rn(v.z - __bfloat162float(hz));
    l23.y = __float2bfloat16_rn(v.w - __bfloat162float(hw));
    *(__nv_bfloat162*)(hi + off)     = h01;
    *(__nv_bfloat162*)(hi + off + 2) = h23;
    *(__nv_bfloat162*)(lo + off)     = l01;
    *(__nv_bfloat162*)(lo + off + 2) = l23;
}

// fp16 variant for the pv V operand
__device__ __forceinline__ void split_store_h(float4 v, __half* hi,
                                              __half* lo, int off)
{
    __half hx = __float2half_rn(v.x), hy = __float2half_rn(v.y);
    __half hz = __float2half_rn(v.z), hw = __float2half_rn(v.w);
    __half2 h01; h01.x = hx; h01.y = hy;
    __half2 h23; h23.x = hz; h23.y = hw;
    __half2 l01, l23;
    l01.x = __float2half_rn(v.x - __half2float(hx));
    l01.y = __float2half_rn(v.y - __half2float(hy));
    l23.x = __float2half_rn(v.z - __half2float(hz));
    l23.y = __float2half_rn(v.w - __half2float(hw));
    *(__half2*)(hi + off)     = h01;
    *(__half2*)(hi + off + 2) = h23;
    *(__half2*)(lo + off)     = l01;
    *(__half2*)(lo + off + 2) = l23;
}

// ---------------------------------------------------------------------------
// Double-buffered HMMA bf16-split NT GEMM:
//   C[M,N] = alpha * A[M,K] * B[N,K]^T   (fp32 in; COUT: 0=fp32 out, 1=fp16 out)
// CTA tile 128 x NT, K-chunk 32, 256 threads (8 warps), 2-stage smem pipeline.
// ASUM=4: A is the elementwise sum of 4 partial buffers at stride apstride.
// ---------------------------------------------------------------------------
#define KC 32
#define SRS 40  // smem row stride in bf16 elements (80 B)

template <int NT, int ASUM, int COUT>
__device__ void hmma_gemm(const float* __restrict__ A, size_t apstride, int lda,
                          const float* __restrict__ B, int ldb,
                          void* __restrict__ Cv, int ldc,
                          int K, float alpha, int m0, int n0)
{
    constexpr int WN = (NT == 128) ? 4 : 2;
    constexpr int WM = 8 / WN;
    constexpr int MT = 128 / WM;
    constexpr int MF = MT / 16;
    constexpr int PB = NT / 32;
    constexpr int AEL = 128 * SRS;
    constexpr int BEL = NT * SRS;
    constexpr int BUFEL = 2 * AEL + 2 * BEL;

    extern __shared__ __nv_bfloat16 sm[];

    const int tid = threadIdx.x;
    const int wid = tid >> 5, lane = tid & 31;
    const int wm = wid / WN, wn = wid % WN;
    const uint32_t ubase = smem_u32(sm);

    const uint32_t aOff = (uint32_t)(wm * MT + (lane & 15)) * (SRS * 2)
                        + (uint32_t)(lane >> 4) * 16;
    const uint32_t bOff = (uint32_t)(wn * 32 + ((lane >> 4) << 3) + (lane & 7)) * (SRS * 2)
                        + (uint32_t)((lane >> 3) & 1) * 16;

    float acc[MF][4][4];
#pragma unroll
    for (int i = 0; i < MF; i++)
#pragma unroll
        for (int j = 0; j < 4; j++)
#pragma unroll
            for (int t = 0; t < 4; t++) acc[i][j][t] = 0.f;

    float4 pa[4], pb[PB];

#define LOAD_AB(k0_)                                                            \
    {                                                                           \
        _Pragma("unroll")                                                       \
        for (int u = 0; u < 4; u++) {                                           \
            int i_ = tid + u * 256;                                             \
            int r_ = i_ >> 3, c4_ = (i_ & 7) << 2;                              \
            size_t idx_ = (size_t)(m0 + r_) * lda + (k0_) + c4_;                \
            float4 v_ = *(const float4*)(A + idx_);                             \
            if (ASUM == 4) {                                                    \
                float4 v1_ = *(const float4*)(A + idx_ + apstride);             \
                float4 v2_ = *(const float4*)(A + idx_ + 2 * apstride);         \
                float4 v3_ = *(const float4*)(A + idx_ + 3 * apstride);         \
                v_.x += v1_.x + v2_.x + v3_.x;                                  \
                v_.y += v1_.y + v2_.y + v3_.y;                                  \
                v_.z += v1_.z + v2_.z + v3_.z;                                  \
                v_.w += v1_.w + v2_.w + v3_.w;                                  \
            }                                                                   \
            pa[u] = v_;                                                         \
        }                                                                       \
        _Pragma("unroll")                                                       \
        for (int u = 0; u < PB; u++) {                                          \
            int i_ = tid + u * 256;                                             \
            int r_ = i_ >> 3, c4_ = (i_ & 7) << 2;                              \
            pb[u] = *(const float4*)(B + (size_t)(n0 + r_) * ldb + (k0_) + c4_);\
        }                                                                       \
    }

#define STORE_BUF(bi_)                                                          \
    {                                                                           \
        __nv_bfloat16* Ah_ = sm + (bi_) * BUFEL;                                \
        __nv_bfloat16* Bh_ = Ah_ + AEL;                                         \
        __nv_bfloat16* Al_ = Bh_ + BEL;                                         \
        __nv_bfloat16* Bl_ = Al_ + AEL;                                         \
        _Pragma("unroll")                                                       \
        for (int u = 0; u < 4; u++) {                                           \
            int i_ = tid + u * 256;                                             \
            int r_ = i_ >> 3, c4_ = (i_ & 7) << 2;                              \
            split_store(pa[u], Ah_, Al_, r_ * SRS + c4_);                       \
        }                                                                       \
        _Pragma("unroll")                                                       \
        for (int u = 0; u < PB; u++) {                                          \
            int i_ = tid + u * 256;                                             \
            int r_ = i_ >> 3, c4_ = (i_ & 7) << 2;                              \
            split_store(pb[u], Bh_, Bl_, r_ * SRS + c4_);                       \
        }                                                                       \
    }

    LOAD_AB(0);
    STORE_BUF(0);
    __syncthreads();

    const int nch = K / KC;
    for (int ch = 0; ch < nch; ch++) {
        if (ch + 1 < nch) LOAD_AB((ch + 1) * KC);

        const uint32_t bb = (uint32_t)((ch & 1) * BUFEL * 2);
        const uint32_t uAh = ubase + bb;
        const uint32_t uBh = uAh + AEL * 2;
        const uint32_t uAl = uBh + BEL * 2;
        const uint32_t uBl = uAl + AEL * 2;

#pragma unroll
        for (int ks = 0; ks < 2; ks++) {
            const uint32_t kb = (uint32_t)(ks * 32);
            uint32_t ah[MF][4], al[MF][4], bh[4][2], bl[4][2];
#pragma unroll
            for (int mf = 0; mf < MF; mf++) {
                uint32_t off = aOff + (uint32_t)(mf * 16) * (SRS * 2) + kb;
                LDSM4(ah[mf], uAh + off);
                LDSM4(al[mf], uAl + off);
            }
#pragma unroll
            for (int g = 0; g < 2; g++) {
                uint32_t off = bOff + (uint32_t)(g * 16) * (SRS * 2) + kb;
                uint32_t th[4], tl[4];
                LDSM4(th, uBh + off);
                LDSM4(tl, uBl + off);
                bh[2 * g][0] = th[0]; bh[2 * g][1] = th[1];
                bh[2 * g + 1][0] = th[2]; bh[2 * g + 1][1] = th[3];
                bl[2 * g][0] = tl[0]; bl[2 * g][1] = tl[1];
                bl[2 * g + 1][0] = tl[2]; bl[2 * g + 1][1] = tl[3];
            }
#pragma unroll
            for (int mf = 0; mf < MF; mf++)
#pragma unroll
                for (int nf = 0; nf < 4; nf++) {
                    MMA16816(acc[mf][nf], ah[mf], bh[nf]);
                    MMA16816(acc[mf][nf], ah[mf], bl[nf]);
                    MMA16816(acc[mf][nf], al[mf], bh[nf]);
                }
        }

        if (ch + 1 < nch) {
            STORE_BUF((ch + 1) & 1);
            __syncthreads();
        }
    }

    // ---- epilogue ----
    const int rbase = m0 + wm * MT + (lane >> 2);
    const int cbase = n0 + wn * 32 + ((lane & 3) << 1);
#pragma unroll
    for (int mf = 0; mf < MF; mf++)
#pragma unroll
        for (int nf = 0; nf < 4; nf++) {
            int r0 = rbase + mf * 16;
            int c = cbase + nf * 8;
            if (COUT == 1) {
                __half* Ch = (__half*)Cv;
                __half2 p0, p1;
                p0.x = __float2half_rn(acc[mf][nf][0] * alpha);
                p0.y = __float2half_rn(acc[mf][nf][1] * alpha);
                p1.x = __float2half_rn(acc[mf][nf][2] * alpha);
                p1.y = __float2half_rn(acc[mf][nf][3] * alpha);
                *(__half2*)(Ch + (size_t)r0 * ldc + c) = p0;
                *(__half2*)(Ch + (size_t)(r0 + 8) * ldc + c) = p1;
            } else {
                float* C = (float*)Cv;
                float2 v0 = {acc[mf][nf][0] * alpha, acc[mf][nf][1] * alpha};
                float2 v1 = {acc[mf][nf][2] * alpha, acc[mf][nf][3] * alpha};
                *(float2*)(C + (size_t)r0 * ldc + c) = v0;
                *(float2*)(C + (size_t)(r0 + 8) * ldc + c) = v1;
            }
        }
#undef LOAD_AB
#undef STORE_BUF
}

#define SMEM_G128 (2 * (2 * 128 * SRS + 2 * 128 * SRS) * 2)  // 81920 B

// ---------------------------------------------------------------------------
// pv GEMM: A fp16 (direct copy), B fp32 split to f16 hi/lo. NT=64, 2-term MMA.
//   C[M,64] = A[M,K](f16) * B[64,K]^T
// ---------------------------------------------------------------------------
template <int DUMMY>
__device__ void hmma_gemm_hA(const __half* __restrict__ A, int lda,
                             const float* __restrict__ B, int ldb,
                             float* __restrict__ C, int ldc,
                             int K, int m0)
{
    constexpr int NT = 64, WN = 2, MT = 32, MF = 2;
    constexpr int AEL = 128 * SRS;
    constexpr int BEL = NT * SRS;
    constexpr int BUFEL = AEL + 2 * BEL;

    extern __shared__ __nv_bfloat16 smb[];
    __half* sm = (__half*)smb;

    const int tid = threadIdx.x;
    const int wid = tid >> 5, lane = tid & 31;
    const int wm = wid / WN, wn = wid % WN;
    const uint32_t ubase = smem_u32(sm);

    const uint32_t aOff = (uint32_t)(wm * MT + (lane & 15)) * (SRS * 2)
                        + (uint32_t)(lane >> 4) * 16;
    const uint32_t bOff = (uint32_t)(wn * 32 + ((lane >> 4) << 3) + (lane & 7)) * (SRS * 2)
                        + (uint32_t)((lane >> 3) & 1) * 16;

    float acc[MF][4][4];
#pragma unroll
    for (int i = 0; i < MF; i++)
#pragma unroll
        for (int j = 0; j < 4; j++)
#pragma unroll
            for (int t = 0; t < 4; t++) acc[i][j][t] = 0.f;

    uint2 pa[4];
    float4 pb[2];

#define LOAD_AB2(k0_)                                                           \
    {                                                                           \
        _Pragma("unroll")                                                       \
        for (int u = 0; u < 4; u++) {                                           \
            int i_ = tid + u * 256;                                             \
            int r_ = i_ >> 3, c4_ = (i_ & 7) << 2;                              \
            pa[u] = *(const uint2*)(A + (size_t)(m0 + r_) * lda + (k0_) + c4_); \
        }                                                                       \
        _Pragma("unroll")                                                       \
        for (int u = 0; u < 2; u++) {                                           \
            int i_ = tid + u * 256;                                             \
            int r_ = i_ >> 3, c4_ = (i_ & 7) << 2;                              \
            pb[u] = *(const float4*)(B + (size_t)r_ * ldb + (k0_) + c4_);       \
        }                                                                       \
    }

#define STORE_BUF2(bi_)                                                         \
    {                                                                           \
        __half* Ah_ = sm + (bi_) * BUFEL;                                       \
        __half* Bh_ = Ah_ + AEL;                                                \
        __half* Bl_ = Bh_ + BEL;                                                \
        _Pragma("unroll")                                                       \
        for (int u = 0; u < 4; u++) {                                           \
            int i_ = tid + u * 256;                                             \
            int r_ = i_ >> 3, c4_ = (i_ & 7) << 2;                              \
            *(uint2*)(Ah_ + r_ * SRS + c4_) = pa[u];                            \
        }                                                                       \
        _Pragma("unroll")                                                       \
        for (int u = 0; u < 2; u++) {                                           \
            int i_ = tid + u * 256;                                             \
            int r_ = i_ >> 3, c4_ = (i_ & 7) << 2;                              \
            split_store_h(pb[u], Bh_, Bl_, r_ * SRS + c4_);                     \
        }                                                                       \
    }

    LOAD_AB2(0);
    STORE_BUF2(0);
    __syncthreads();

    const int nch = K / KC;
    for (int ch = 0; ch < nch; ch++) {
        if (ch + 1 < nch) LOAD_AB2((ch + 1) * KC);

        const uint32_t bb = (uint32_t)((ch & 1) * BUFEL * 2);
        const uint32_t uAh = ubase + bb;
        const uint32_t uBh = uAh + AEL * 2;
        const uint32_t uBl = uBh + BEL * 2;

#pragma unroll
        for (int ks = 0; ks < 2; ks++) {
            const uint32_t kb = (uint32_t)(ks * 32);
            uint32_t ah[MF][4], bh[4][2], bl[4][2];
#pragma unroll
            for (int mf = 0; mf < MF; mf++) {
                uint32_t off = aOff + (uint32_t)(mf * 16) * (SRS * 2) + kb;
                LDSM4(ah[mf], uAh + off);
            }
#pragma unroll
            for (int g = 0; g < 2; g++) {
                uint32_t off = bOff + (uint32_t)(g * 16) * (SRS * 2) + kb;
                uint32_t th[4], tl[4];
                LDSM4(th, uBh + off);
                LDSM4(tl, uBl + off);
                bh[2 * g][0] = th[0]; bh[2 * g][1] = th[1];
                bh[2 * g + 1][0] = th[2]; bh[2 * g + 1][1] = th[3];
                bl[2 * g][0] = tl[0]; bl[2 * g][1] = tl[1];
                bl[2 * g + 1][0] = tl[2]; bl[2 * g + 1][1] = tl[3];
            }
#pragma unroll
            for (int mf = 0; mf < MF; mf++)
#pragma unroll
                for (int nf = 0; nf < 4; nf++) {
                    MMA16816H(acc[mf][nf], ah[mf], bh[nf]);
                    MMA16816H(acc[mf][nf], ah[mf], bl[nf]);
                }
        }

        if (ch + 1 < nch) {
            STORE_BUF2((ch + 1) & 1);
            __syncthreads();
        }
    }

    const int rbase = m0 + wm * MT + (lane >> 2);
    const int cbase = wn * 32 + ((lane & 3) << 1);
#pragma unroll
    for (int mf = 0; mf < MF; mf++)
#pragma unroll
        for (int nf = 0; nf < 4; nf++) {
            int r0 = rbase + mf * 16;
            int c = cbase + nf * 8;
            float2 v0 = {acc[mf][nf][0], acc[mf][nf][1]};
            float2 v1 = {acc[mf][nf][2], acc[mf][nf][3]};
            *(float2*)(C + (size_t)r0 * ldc + c) = v0;
            *(float2*)(C + (size_t)(r0 + 8) * ldc + c) = v1;
        }
#undef LOAD_AB2
#undef STORE_BUF2
}

#define SMEM_PV (2 * (128 * SRS + 2 * 64 * SRS) * 2)  // 40960 B

// ---------------------------------------------------------------------------
// Transpose: dst[c, r] = src[r, c]
// ---------------------------------------------------------------------------
__global__ __launch_bounds__(256) void k_transpose(const float* __restrict__ src,
                                                   float* __restrict__ dst, int R, int C)
{
    __shared__ float t[32][33];
    const float* s = src + (size_t)blockIdx.z * R * C;
    float* d = dst + (size_t)blockIdx.z * R * C;
    int c0 = blockIdx.x * 32, r0 = blockIdx.y * 32;
    for (int dy = threadIdx.y; dy < 32; dy += 8)
        t[dy][threadIdx.x] = s[(size_t)(r0 + dy) * C + c0 + threadIdx.x];
    __syncthreads();
    for (int dy = threadIdx.y; dy < 32; dy += 8)
        d[(size_t)(c0 + dy) * R + r0 + threadIdx.x] = t[threadIdx.x][dy];
}

// ---------------------------------------------------------------------------
// Stage kernels
// ---------------------------------------------------------------------------
__global__ __launch_bounds__(256) void k_qkv_mma(const float* __restrict__ x)
{
    int which = blockIdx.z;
    const float* W = (which == 0) ? g_wqt : (which == 1) ? g_wkt : g_wvt;
    float* O = (which == 0) ? g_q : (which == 1) ? g_k : g_v;
    float alpha = (which == 0) ? 0.125f : 1.0f;
    hmma_gemm<128, 1, 0>(x, 0, DM, W, DM, O, DM, DM, alpha,
                         blockIdx.y * 128, blockIdx.x * 128);
}

__global__ __launch_bounds__(256) void k_scores_mma()
{
    int z = blockIdx.z, b = z >> 3, h = z & 7;
    const float* A = g_q + (size_t)b * PLEN * DM + h * DH;
    const float* B = g_k + (size_t)b * PLEN * DM + h * DH;
    __half* C = g_S + (size_t)z * PLEN * PLEN;
    hmma_gemm<128, 1, 1>(A, 0, DM, B, DM, C, PLEN, DH, 1.0f,
                         blockIdx.y * 128, blockIdx.x * 128);
}

__global__ __launch_bounds__(256) void k_pv_mma()
{
    int kidx = blockIdx.x;
    int z = blockIdx.z, b = z >> 3, g = z & 7;
    const __half* A = g_Sh + (size_t)z * PLEN * PLEN + kidx * (PLEN / KSPLIT);
    const float* B = g_vt + (size_t)b * DM * PLEN + (size_t)g * DH * PLEN
                   + kidx * (PLEN / KSPLIT);
    float* C = g_ohp + (size_t)kidx * PSTRIDE + (size_t)b * PLEN * DM + g * DH;
    hmma_gemm_hA<0>(A, PLEN, B, PLEN, C, DM, PLEN / KSPLIT, blockIdx.y * 128);
}

__global__ __launch_bounds__(256) void k_proj_mma(float* __restrict__ out)
{
    hmma_gemm<128, 4, 0>(g_ohp, PSTRIDE, DM, g_wpt, DM, out, DM, DM, 1.0f,
                         blockIdx.y * 128, blockIdx.x * 128);
}

// ---------------------------------------------------------------------------
// Stage 3: head-mix (W1) -> softmax -> head-mix (W2, /l folded).
// Reads fp16 g_S, writes fp16 g_Sh. 512 thr, 2 warps per head.
// ---------------------------------------------------------------------------
__device__ __forceinline__ float4 ld4h(const __half* p) {
    uint2 u = *(const uint2*)p;
    __half2 a = *(__half2*)&u.x;
    __half2 b = *(__half2*)&u.y;
    float4 r;
    r.x = __half2float(a.x); r.y = __half2float(a.y);
    r.z = __half2float(b.x); r.w = __half2float(b.y);
    return r;
}
__device__ __forceinline__ void st4h(__half* p, float4 v) {
    __half2 a, b;
    a.x = __float2half_rn(v.x); a.y = __float2half_rn(v.y);
    b.x = __float2half_rn(v.z); b.y = __float2half_rn(v.w);
    uint2 u;
    u.x = *(uint32_t*)&a; u.y = *(uint32_t*)&b;
    *(uint2*)p = u;
}

__global__ __launch_bounds__(512) void k_mix_softmax(
    const float* __restrict__ W1, const float* __restrict__ W2)
{
    extern __shared__ float smix[];  // [8][2048]
    __shared__ float w1s[64], w2l[64], redm[16], reds[16];

    const int tid = threadIdx.x;
    const int i = blockIdx.x, b = blockIdx.y;

    if (tid < 64) w1s[tid] = W1[tid];
    __syncthreads();

    const __half* Srow = g_S + (size_t)b * NH * PLEN * PLEN + (size_t)i * PLEN;
    __half* Orow = g_Sh + (size_t)b * NH * PLEN * PLEN + (size_t)i * PLEN;
    const int j4 = tid << 2;

    // ---- mix1 ----
    float4 r[8];
#pragma unroll
    for (int h = 0; h < 8; h++)
        r[h] = ld4h(Srow + (size_t)h * PLEN * PLEN + j4);
#pragma unroll
    for (int g = 0; g < 8; g++) {
        float4 a = {0.f, 0.f, 0.f, 0.f};
#pragma unroll
        for (int h = 0; h < 8; h++) {
            float w = w1s[h * 8 + g];
            a.x += w * r[h].x; a.y += w * r[h].y;
            a.z += w * r[h].z; a.w += w * r[h].w;
        }
        *(float4*)(smix + g * PLEN + j4) = a;
    }
    __syncthreads();

    // ---- softmax: 2 warps per head ----
    const int wid = tid >> 5, lane = tid & 31;
    const int g = wid >> 1;
    const int t64 = ((wid & 1) << 5) + lane;
    float* sg = smix + g * PLEN;

    float m = -1e30f;
#pragma unroll
    for (int k2 = 0; k2 < 32; k2++) m = fmaxf(m, sg[t64 + (k2 << 6)]);
#pragma unroll
    for (int o = 16; o; o >>= 1) m = fmaxf(m, __shfl_xor_sync(0xffffffffu, m, o));
    if (lane == 0) redm[wid] = m;
    __syncthreads();
    m = fmaxf(redm[g << 1], redm[(g << 1) + 1]);

    float l = 0.f;
#pragma unroll
    for (int k2 = 0; k2 < 32; k2++) {
        int idx = t64 + (k2 << 6);
        float e = __expf(sg[idx] - m);
        sg[idx] = e;
        l += e;
    }
#pragma unroll
    for (int o = 16; o; o >>= 1) l += __shfl_xor_sync(0xffffffffu, l, o);
    if (lane == 0) reds[wid] = l;
    __syncthreads();

    if (tid < 64) {
        int h = tid >> 3;
        w2l[tid] = W2[tid] / (reds[h << 1] + reds[(h << 1) + 1]);
    }
    __syncthreads();

    // ---- mix2 -> fp16 out ----
#pragma unroll
    for (int h = 0; h < 8; h++) r[h] = *(const float4*)(smix + h * PLEN + j4);
#pragma unroll
    for (int gp = 0; gp < 8; gp++) {
        float4 a = {0.f, 0.f, 0.f, 0.f};
#pragma unroll
        for (int h = 0; h < 8; h++) {
            float w = w2l[h * 8 + gp];
            a.x += w * r[h].x; a.y += w * r[h].y;
            a.z += w * r[h].z; a.w += w * r[h].w;
        }
        st4h(Orow + (size_t)gp * PLEN * PLEN + j4, a);
    }
}

// ---------------------------------------------------------------------------
extern "C" void kernel_launch(void* const* d_in, const int* in_sizes, int n_in,
                              void* d_out, int out_size)
{
    const float* x     = (const float*)d_in[0];
    const float* Wq    = (const float*)d_in[1];
    const float* Wk    = (const float*)d_in[2];
    const float* Wv    = (const float*)d_in[3];
    const float* W1    = (const float*)d_in[4];
    const float* W2    = (const float*)d_in[5];
    const float* Wproj = (const float*)d_in[6];
    float* out = (float*)d_out;

    cudaFuncSetAttribute(k_mix_softmax, cudaFuncAttributeMaxDynamicSharedMemorySize, 65536);
    cudaFuncSetAttribute(k_qkv_mma,    cudaFuncAttributeMaxDynamicSharedMemorySize, SMEM_G128);
    cudaFuncSetAttribute(k_scores_mma, cudaFuncAttributeMaxDynamicSharedMemorySize, SMEM_G128);
    cudaFuncSetAttribute(k_pv_mma,     cudaFuncAttributeMaxDynamicSharedMemorySize, SMEM_PV);
    cudaFuncSetAttribute(k_proj_mma,   cudaFuncAttributeMaxDynamicSharedMemorySize, SMEM_G128);

    float* wqt = nullptr; cudaGetSymbolAddress((void**)&wqt, g_wqt);
    float* wkt = nullptr; cudaGetSymbolAddress((void**)&wkt, g_wkt);
    float* wvt = nullptr; cudaGetSymbolAddress((void**)&wvt, g_wvt);
    float* wpt = nullptr; cudaGetSymbolAddress((void**)&wpt, g_wpt);
    float* vp  = nullptr; cudaGetSymbolAddress((void**)&vp,  g_v);
    float* vtp = nullptr; cudaGetSymbolAddress((void**)&vtp, g_vt);

    k_transpose<<<dim3(16, 16, 1), dim3(32, 8)>>>(Wq, wqt, DM, DM);
    k_transpose<<<dim3(16, 16, 1), dim3(32, 8)>>>(Wk, wkt, DM, DM);
    k_transpose<<<dim3(16, 16, 1), dim3(32, 8)>>>(Wv, wvt, DM, DM);
    k_transpose<<<dim3(16, 16, 1), dim3(32, 8)>>>(Wproj, wpt, DM, DM);

    k_qkv_mma<<<dim3(4, 32, 3), 256, SMEM_G128>>>(x);
    k_transpose<<<dim3(16, 64, 2), dim3(32, 8)>>>(vp, vtp, PLEN, DM);
    k_scores_mma<<<dim3(16, 16, 16), 256, SMEM_G128>>>();
    k_mix_softmax<<<dim3(2048, 2, 1), 512, 65536>>>(W1, W2);
    k_pv_mma<<<dim3(KSPLIT, 16, 16), 256, SMEM_PV>>>();
    k_proj_mma<<<dim3(4, 32, 1), 256, SMEM_G128>>>(out);
}